// round 3
// baseline (speedup 1.0000x reference)
#include <cuda_runtime.h>
#include <math.h>

// Problem constants
#define BATCH 8
#define DIM   64
#define HID   128
#define C2    256      // 2*HID
#define IMG_H 128
#define IMG_W 128
#define HW    16384    // 128*128

// Scratch for u = project_in(x): (B, C2, H, W) fp32 = 128 MiB (device global, no alloc)
__device__ float g_u[(size_t)BATCH * C2 * HW];

// ---------------- packed f32x2 helpers (sm_103a FFMA2) ----------------
__device__ __forceinline__ unsigned long long pk2(float v) {
    unsigned long long r;
    asm("mov.b64 %0, {%1, %1};" : "=l"(r) : "f"(v));
    return r;
}
__device__ __forceinline__ unsigned long long fma2(unsigned long long a,
                                                   unsigned long long b,
                                                   unsigned long long c) {
    unsigned long long d;
    asm("fma.rn.f32x2 %0, %1, %2, %3;" : "=l"(d) : "l"(a), "l"(b), "l"(c));
    return d;
}
__device__ __forceinline__ void upk(unsigned long long v, float& lo, float& hi) {
    asm("mov.b64 {%0, %1}, %2;" : "=f"(lo), "=f"(hi) : "l"(v));
}

// =====================================================================
// Kernel 1: u[b,o,p] = sum_k W_in[o,k] * x[b,k,p]
// CTA: 64 out-channels x 128 pixels, 256 threads (16 px-groups x 16 o-groups)
// Thread tile: 4 o x 8 px, accumulated as 16 packed f32x2 registers.
// =====================================================================
__global__ void __launch_bounds__(256) k_proj_in(const float* __restrict__ x,
                                                 const float* __restrict__ W_in) {
    __shared__ float xs[64 * 128];   // [k][px]  32 KB
    __shared__ float Ws[64 * 64];    // [k][o]   16 KB

    const int t  = threadIdx.x;
    const int b  = blockIdx.z;
    const int o0 = blockIdx.y * 64;
    const int p0 = blockIdx.x * 128;

    // Stage x tile: 64 channels x 128 contiguous pixels (float4, coalesced)
    {
        const float4* xg = (const float4*)(x + ((size_t)b * DIM) * HW + p0);
        float4* xs4 = (float4*)xs;
#pragma unroll
        for (int i = 0; i < 8; i++) {
            int idx = t + i * 256;            // 0..2047
            int k   = idx >> 5;               // /32 float4 per row
            int c4  = idx & 31;
            xs4[idx] = xg[(size_t)k * (HW / 4) + c4];
        }
    }
    // Stage W_in transposed: Ws[k][o] (coalesced global reads)
#pragma unroll
    for (int i = 0; i < 16; i++) {
        int idx = t + i * 256;                // 0..4095
        int o = idx >> 6, k = idx & 63;
        Ws[k * 64 + o] = W_in[(o0 + o) * 64 + k];
    }
    __syncthreads();

    const int tx = t & 15;        // pixel group
    const int ty = t >> 4;        // o group
    const int ob = ty * 4;
    const int pb = tx * 8;

    unsigned long long acc[4][4];
#pragma unroll
    for (int i = 0; i < 4; i++)
#pragma unroll
        for (int j = 0; j < 4; j++) acc[i][j] = 0ull;

#pragma unroll 4
    for (int k = 0; k < 64; k++) {
        float4 w = *(const float4*)&Ws[k * 64 + ob];
        const ulonglong2* xr = (const ulonglong2*)&xs[k * 128 + pb];
        ulonglong2 xv0 = xr[0];
        ulonglong2 xv1 = xr[1];
        unsigned long long wp0 = pk2(w.x), wp1 = pk2(w.y),
                           wp2 = pk2(w.z), wp3 = pk2(w.w);
        acc[0][0] = fma2(wp0, xv0.x, acc[0][0]);
        acc[0][1] = fma2(wp0, xv0.y, acc[0][1]);
        acc[0][2] = fma2(wp0, xv1.x, acc[0][2]);
        acc[0][3] = fma2(wp0, xv1.y, acc[0][3]);
        acc[1][0] = fma2(wp1, xv0.x, acc[1][0]);
        acc[1][1] = fma2(wp1, xv0.y, acc[1][1]);
        acc[1][2] = fma2(wp1, xv1.x, acc[1][2]);
        acc[1][3] = fma2(wp1, xv1.y, acc[1][3]);
        acc[2][0] = fma2(wp2, xv0.x, acc[2][0]);
        acc[2][1] = fma2(wp2, xv0.y, acc[2][1]);
        acc[2][2] = fma2(wp2, xv1.x, acc[2][2]);
        acc[2][3] = fma2(wp2, xv1.y, acc[2][3]);
        acc[3][0] = fma2(wp3, xv0.x, acc[3][0]);
        acc[3][1] = fma2(wp3, xv0.y, acc[3][1]);
        acc[3][2] = fma2(wp3, xv1.x, acc[3][2]);
        acc[3][3] = fma2(wp3, xv1.y, acc[3][3]);
    }

    // Store 4 o-rows x 8 px (two 16B stores per row; packed layout == float layout)
#pragma unroll
    for (int oi = 0; oi < 4; oi++) {
        float* dst = g_u + ((size_t)b * C2 + (o0 + ob + oi)) * HW + p0 + pb;
        ulonglong2 v0, v1;
        v0.x = acc[oi][0]; v0.y = acc[oi][1];
        v1.x = acc[oi][2]; v1.y = acc[oi][3];
        ((ulonglong2*)dst)[0] = v0;
        ((ulonglong2*)dst)[1] = v1;
    }
}

// =====================================================================
// Kernel 2: dynamic depthwise 3x3 + exact GELU gate + project_out
// CTA: one batch, 32x8 spatial tile. 256 threads = 32 px_x x 8 px_y
// (warp == one full 32-px row -> conflict-free halo LDS).
// Per channel pair c (gelu branch) / c+128 (gate branch):
//   stage 34x10 halos of u, 3x3 conv with per-(b,c) kernel, gate,
//   rank-1 update of 64 output-channel accumulators (32 packed f32x2).
// =====================================================================
__global__ void __launch_bounds__(256) k_dw_gate_out(const float* __restrict__ genk,
                                                     const float* __restrict__ dwkg,
                                                     const float* __restrict__ lam,
                                                     const float* __restrict__ W_out,
                                                     float* __restrict__ out) {
    __shared__ float kc[C2 * 9];        // combined dynamic kernels   9216 B
    __shared__ float Wo[HID * 64];      // [c][o]                    32768 B
    __shared__ float ua[10 * 34];       // halo, gelu branch          1360 B
    __shared__ float ub[10 * 34];       // halo, gate branch          1360 B

    const int t  = threadIdx.x;
    const int b  = blockIdx.z;
    const int x0 = blockIdx.x * 32;
    const int y0 = blockIdx.y * 8;

    // Combined per-(b,c) kernel: dw + lambda*gen   (layouts: [c*9+tap])
    for (int idx = t; idx < C2 * 9; idx += 256) {
        int c = idx / 9;
        kc[idx] = dwkg[idx] + lam[c] * genk[b * (C2 * 9) + idx];
    }
    // W_out (64,128) -> Wo[c][o]
    for (int idx = t; idx < 64 * HID; idx += 256) {
        int o = idx >> 7, c = idx & 127;
        Wo[c * 64 + o] = W_out[idx];
    }
    __syncthreads();

    const int px = t & 31;
    const int py = t >> 5;

    unsigned long long acc[32];
#pragma unroll
    for (int j = 0; j < 32; j++) acc[j] = 0ull;

    for (int c = 0; c < HID; c++) {
        // Stage halos (zero-padded SAME borders)
        const float* Ua = g_u + ((size_t)b * C2 + c) * HW;
        const float* Ub = Ua + (size_t)HID * HW;
        for (int idx = t; idx < 340; idx += 256) {
            int r  = idx / 34;
            int cc = idx - r * 34;
            int gy = y0 - 1 + r;
            int gx = x0 - 1 + cc;
            bool ok = ((unsigned)gy < 128u) && ((unsigned)gx < 128u);
            int goff = gy * IMG_W + gx;
            ua[idx] = ok ? Ua[goff] : 0.0f;
            ub[idx] = ok ? Ub[goff] : 0.0f;
        }
        __syncthreads();

        // 3x3 cross-correlation at (py,px) on both branches
        float va = 0.0f, vb = 0.0f;
        const float* ka = &kc[c * 9];
        const float* kb = &kc[(c + HID) * 9];
        const int base = py * 34 + px;
#pragma unroll
        for (int dy = 0; dy < 3; dy++) {
#pragma unroll
            for (int dx = 0; dx < 3; dx++) {
                float av = ua[base + dy * 34 + dx];
                float bv = ub[base + dy * 34 + dx];
                va = fmaf(ka[dy * 3 + dx], av, va);
                vb = fmaf(kb[dy * 3 + dx], bv, vb);
            }
        }

        // exact GELU(va) * vb
        float g = 0.5f * va * (1.0f + erff(va * 0.7071067811865476f)) * vb;
        unsigned long long g2 = pk2(g);

        // out[o] += W_out[o][c] * g   (broadcast LDS.128, packed FMA)
        const ulonglong2* wr = (const ulonglong2*)&Wo[c * 64];
#pragma unroll
        for (int j = 0; j < 16; j++) {
            ulonglong2 wv = wr[j];
            acc[2 * j]     = fma2(wv.x, g2, acc[2 * j]);
            acc[2 * j + 1] = fma2(wv.y, g2, acc[2 * j + 1]);
        }
        __syncthreads();   // protect halo buffers for next c
    }

    // Epilogue: thread owns pixel (y0+py, x0+px), all 64 out channels
    float* op = out + (size_t)b * DIM * HW + (y0 + py) * IMG_W + (x0 + px);
#pragma unroll
    for (int j = 0; j < 32; j++) {
        float lo, hi;
        upk(acc[j], lo, hi);
        op[(size_t)(2 * j) * HW]     = lo;
        op[(size_t)(2 * j + 1) * HW] = hi;
    }
}

// =====================================================================
// Launch: two kernels on the default stream (graph-capturable, no allocs)
// Inputs (metadata order): x, gen_kernel, W_in, dw_kernel, lambda_dw, W_out
// =====================================================================
extern "C" void kernel_launch(void* const* d_in, const int* in_sizes, int n_in,
                              void* d_out, int out_size) {
    const float* x     = (const float*)d_in[0];
    const float* genk  = (const float*)d_in[1];
    const float* W_in  = (const float*)d_in[2];
    const float* dwk   = (const float*)d_in[3];
    const float* lam   = (const float*)d_in[4];
    const float* W_out = (const float*)d_in[5];
    float* out = (float*)d_out;

    // K1: grid (px tiles, o tiles, batch) = (16384/128, 256/64, 8)
    dim3 g1(HW / 128, C2 / 64, BATCH);
    k_proj_in<<<g1, 256>>>(x, W_in);

    // K2: grid (x tiles, y tiles, batch) = (128/32, 128/8, 8)
    dim3 g2(IMG_W / 32, IMG_H / 8, BATCH);
    k_dw_gate_out<<<g2, 256>>>(genk, dwk, lam, W_out, out);
}

// round 6
// speedup vs baseline: 1.1923x; 1.1923x over previous
#include <cuda_runtime.h>
#include <math.h>

// Problem constants
#define BATCH 8
#define DIM   64
#define HID   128
#define C2    256      // 2*HID
#define IMG_H 128
#define IMG_W 128
#define HW    16384    // 128*128

// Scratch for u = project_in(x): (B, C2, H, W) fp32 = 128 MiB (device global, no alloc)
__device__ float g_u[(size_t)BATCH * C2 * HW];

// ---------------- packed f32x2 helpers (sm_103a FFMA2) ----------------
__device__ __forceinline__ unsigned long long pk2(float v) {
    unsigned long long r;
    asm("mov.b64 %0, {%1, %1};" : "=l"(r) : "f"(v));
    return r;
}
__device__ __forceinline__ unsigned long long fma2(unsigned long long a,
                                                   unsigned long long b,
                                                   unsigned long long c) {
    unsigned long long d;
    asm("fma.rn.f32x2 %0, %1, %2, %3;" : "=l"(d) : "l"(a), "l"(b), "l"(c));
    return d;
}

// ---------------- cp.async helpers ----------------
__device__ __forceinline__ void cp16(void* smem_dst, const void* gmem_src, int src_sz) {
    unsigned int s = (unsigned int)__cvta_generic_to_shared(smem_dst);
    asm volatile("cp.async.ca.shared.global [%0], [%1], 16, %2;\n"
                 :: "r"(s), "l"(gmem_src), "r"(src_sz));
}
__device__ __forceinline__ void cp_commit() {
    asm volatile("cp.async.commit_group;\n");
}
template <int N>
__device__ __forceinline__ void cp_wait() {
    asm volatile("cp.async.wait_group %0;\n" :: "n"(N));
}

// =====================================================================
// Kernel 1: u[b,o,p] = sum_k W_in[o,k] * x[b,k,p]
// CTA: 64 out-channels x 128 pixels, 512 threads.
// Thread tile: 2 o x 8 px -> 8 packed f32x2 accumulators (low reg pressure).
// x tile staged via cp.async (all dst/src 16B aligned).
// =====================================================================
__global__ void __launch_bounds__(512) k_proj_in(const float* __restrict__ x,
                                                 const float* __restrict__ W_in) {
    __shared__ float xs[64 * 128];   // [k][px]  32 KB
    __shared__ float Ws[64 * 64];    // [k][o]   16 KB

    const int t  = threadIdx.x;
    const int b  = blockIdx.z;
    const int o0 = blockIdx.y * 64;
    const int p0 = blockIdx.x * 128;

    // Stage x tile with cp.async: 64 ch x 32 16B-chunks = 2048 chunks, 4/thread
    {
        const float* xg = x + ((size_t)b * DIM) * HW + p0;
#pragma unroll
        for (int i = 0; i < 4; i++) {
            int idx = t + i * 512;            // 0..2047
            int k   = idx >> 5;
            int c4  = idx & 31;
            cp16(&xs[idx * 4], xg + (size_t)k * HW + c4 * 4, 16);
        }
        cp_commit();
    }
    // Stage W_in transposed: Ws[k][o] (plain loads, overlap with cp.async)
#pragma unroll
    for (int i = 0; i < 8; i++) {
        int idx = t + i * 512;                // 0..4095
        int o = idx >> 6, k = idx & 63;
        Ws[k * 64 + o] = W_in[(o0 + o) * 64 + k];
    }
    cp_wait<0>();
    __syncthreads();

    const int tx = t & 15;        // pixel group (8 px)
    const int ty = t >> 4;        // o group (2 o), 0..31
    const int ob = ty * 2;
    const int pb = tx * 8;

    unsigned long long acc[2][4];
#pragma unroll
    for (int i = 0; i < 2; i++)
#pragma unroll
        for (int j = 0; j < 4; j++) acc[i][j] = 0ull;

#pragma unroll 4
    for (int k = 0; k < 64; k++) {
        float2 w = *(const float2*)&Ws[k * 64 + ob];
        const ulonglong2* xr = (const ulonglong2*)&xs[k * 128 + pb];
        ulonglong2 xv0 = xr[0];
        ulonglong2 xv1 = xr[1];
        unsigned long long wp0 = pk2(w.x), wp1 = pk2(w.y);
        acc[0][0] = fma2(wp0, xv0.x, acc[0][0]);
        acc[0][1] = fma2(wp0, xv0.y, acc[0][1]);
        acc[0][2] = fma2(wp0, xv1.x, acc[0][2]);
        acc[0][3] = fma2(wp0, xv1.y, acc[0][3]);
        acc[1][0] = fma2(wp1, xv0.x, acc[1][0]);
        acc[1][1] = fma2(wp1, xv0.y, acc[1][1]);
        acc[1][2] = fma2(wp1, xv1.x, acc[1][2]);
        acc[1][3] = fma2(wp1, xv1.y, acc[1][3]);
    }

#pragma unroll
    for (int oi = 0; oi < 2; oi++) {
        float* dst = g_u + ((size_t)b * C2 + (o0 + ob + oi)) * HW + p0 + pb;
        ulonglong2 v0, v1;
        v0.x = acc[oi][0]; v0.y = acc[oi][1];
        v1.x = acc[oi][2]; v1.y = acc[oi][3];
        ((ulonglong2*)dst)[0] = v0;
        ((ulonglong2*)dst)[1] = v1;
    }
}

// =====================================================================
// Kernel 2: dynamic depthwise 3x3 + exact GELU gate + project_out
// CTA = one image row (batch b, row y), 256 threads.
// Halo layout: interior pixel x at smem index x+4 (16B-aligned cp.async
// destinations); left pad at index 3, right pad at index 132; row stride
// HROW=136. Edge zeros written once in the prologue, never overwritten.
//   Per channel c: cp.async double-buffered 3x(128+pad) halos of both
//   branches; threads 0..127 do 3x3 conv + exact-GELU gate -> gs[128];
//   then all 256 threads do a rank-1 update of the 64x128 output tile
//   (thread tile 4o x 8px = 16 packed f32x2 accumulators).
// =====================================================================
#define HROW 136                    // padded halo row stride (floats)
#define HBR  (3 * HROW)             // one branch = 3 rows = 408 floats

__global__ void __launch_bounds__(256) k_dw_gate_out(const float* __restrict__ genk,
                                                     const float* __restrict__ dwkg,
                                                     const float* __restrict__ lam,
                                                     const float* __restrict__ W_out,
                                                     float* __restrict__ out) {
    __shared__ float kc[C2 * 9];            //  9216 B
    __shared__ float Wo[HID * 64];          // 32768 B
    __shared__ float halo[2][2 * HBR];      //  6528 B  [buf][branch*HBR + r*HROW + col]
    __shared__ float gs[128];               //   512 B

    const int t = threadIdx.x;
    const int b = blockIdx.z;
    const int y = blockIdx.x;               // image row 0..127

    // Zero halos (pad columns 0..3 and 132..135 must stay zero: SAME padding)
    for (int i = t; i < 2 * 2 * HBR; i += 256) ((float*)halo)[i] = 0.0f;
    // Combined per-(b,c) kernels: dw + lambda*gen
    for (int idx = t; idx < C2 * 9; idx += 256) {
        int c = idx / 9;
        kc[idx] = dwkg[idx] + lam[c] * genk[b * (C2 * 9) + idx];
    }
    // W_out (64,128) -> Wo[c][o]
    for (int idx = t; idx < 64 * HID; idx += 256) {
        int o = idx >> 7, c = idx & 127;
        Wo[c * 64 + o] = W_out[idx];
    }
    __syncthreads();   // zeros + kc + Wo visible before any cp.async overwrites halos

    // Halo staging: 2 branches x 3 rows x 32 chunks = 192 cp.asyncs, 1/thread.
    // dst offset = br*408 + r*136 + 4 + 4*ch  -> multiple of 4 floats = 16B aligned.
    const float* Ub = g_u + ((size_t)b * C2) * HW;
    auto stage = [&](int c, int buf) {
        if (t < 192) {
            int br = t / 96;
            int r  = (t - br * 96) >> 5;
            int ch = t & 31;
            int gy = y + r - 1;
            bool ok = (unsigned)gy < 128u;
            int gyc = ok ? gy : 0;
            const float* src = Ub + ((size_t)(c + br * HID)) * HW + gyc * IMG_W + ch * 4;
            float* dst = &halo[buf][br * HBR + r * HROW + 4 + ch * 4];
            cp16(dst, src, ok ? 16 : 0);   // src_sz=0 zero-fills (keeps SAME pad)
        }
        cp_commit();
    };

    stage(0, 0);   // prologue prefetch

    const int tp = t & 15;        // px group
    const int to = t >> 4;        // o group 0..15
    const int ob = to * 4;
    const int pb = tp * 8;

    unsigned long long acc[16];
#pragma unroll
    for (int j = 0; j < 16; j++) acc[j] = 0ull;

    for (int c = 0; c < HID; c++) {
        int nc = c + 1;
        if (nc < HID) stage(nc, nc & 1);
        else cp_commit();          // keep group accounting uniform
        cp_wait<1>();              // channel c's halos complete
        __syncthreads();           // (S1) halos visible; protects gs from last GEMM

        // ---- conv + exact-GELU gate (threads 0..127, one pixel each) ----
        if (t < 128) {
            const float* A  = &halo[c & 1][0];
            const float* Bv = &halo[c & 1][HBR];
            const float* ka = &kc[c * 9];
            const float* kb = &kc[(c + HID) * 9];
            float va = 0.0f, vb = 0.0f;
#pragma unroll
            for (int r = 0; r < 3; r++) {
#pragma unroll
                for (int dx = 0; dx < 3; dx++) {
                    // logical x = t + dx - 1 -> smem index t + dx + 3
                    va = fmaf(ka[r * 3 + dx], A[r * HROW + t + 3 + dx], va);
                    vb = fmaf(kb[r * 3 + dx], Bv[r * HROW + t + 3 + dx], vb);
                }
            }
            gs[t] = 0.5f * va * (1.0f + erff(va * 0.7071067811865476f)) * vb;
        }
        __syncthreads();           // (S2) gs visible

        // ---- rank-1 GEMM update: acc[o][px] += Wo[c][o] * gs[px] ----
        float4 w = *(const float4*)&Wo[c * 64 + ob];
        unsigned long long wp0 = pk2(w.x), wp1 = pk2(w.y),
                           wp2 = pk2(w.z), wp3 = pk2(w.w);
        const ulonglong2* gp = (const ulonglong2*)&gs[pb];
        ulonglong2 g0 = gp[0], g1 = gp[1];
        acc[0]  = fma2(wp0, g0.x, acc[0]);
        acc[1]  = fma2(wp0, g0.y, acc[1]);
        acc[2]  = fma2(wp0, g1.x, acc[2]);
        acc[3]  = fma2(wp0, g1.y, acc[3]);
        acc[4]  = fma2(wp1, g0.x, acc[4]);
        acc[5]  = fma2(wp1, g0.y, acc[5]);
        acc[6]  = fma2(wp1, g1.x, acc[6]);
        acc[7]  = fma2(wp1, g1.y, acc[7]);
        acc[8]  = fma2(wp2, g0.x, acc[8]);
        acc[9]  = fma2(wp2, g0.y, acc[9]);
        acc[10] = fma2(wp2, g1.x, acc[10]);
        acc[11] = fma2(wp2, g1.y, acc[11]);
        acc[12] = fma2(wp3, g0.x, acc[12]);
        acc[13] = fma2(wp3, g0.y, acc[13]);
        acc[14] = fma2(wp3, g1.x, acc[14]);
        acc[15] = fma2(wp3, g1.y, acc[15]);
    }

    // Epilogue: thread owns 4 o-rows x 8 px of row y
#pragma unroll
    for (int oi = 0; oi < 4; oi++) {
        float* dst = out + ((size_t)b * DIM + (ob + oi)) * HW + y * IMG_W + pb;
        ulonglong2 v0, v1;
        v0.x = acc[oi * 4 + 0]; v0.y = acc[oi * 4 + 1];
        v1.x = acc[oi * 4 + 2]; v1.y = acc[oi * 4 + 3];
        ((ulonglong2*)dst)[0] = v0;
        ((ulonglong2*)dst)[1] = v1;
    }
}

// =====================================================================
// Launch (graph-capturable, no allocs)
// Inputs: x, gen_kernel, W_in, dw_kernel, lambda_dw, W_out
// =====================================================================
extern "C" void kernel_launch(void* const* d_in, const int* in_sizes, int n_in,
                              void* d_out, int out_size) {
    const float* x     = (const float*)d_in[0];
    const float* genk  = (const float*)d_in[1];
    const float* W_in  = (const float*)d_in[2];
    const float* dwk   = (const float*)d_in[3];
    const float* lam   = (const float*)d_in[4];
    const float* W_out = (const float*)d_in[5];
    float* out = (float*)d_out;

    dim3 g1(HW / 128, C2 / 64, BATCH);      // (128, 4, 8)
    k_proj_in<<<g1, 512>>>(x, W_in);

    dim3 g2(IMG_H, 1, BATCH);               // one CTA per image row
    k_dw_gate_out<<<g2, 256>>>(genk, dwk, lam, W_out, out);
}

// round 7
// speedup vs baseline: 1.8738x; 1.5716x over previous
#include <cuda_runtime.h>
#include <math.h>

// Problem constants
#define BATCH 8
#define DIM   64
#define HID   128
#define C2    256      // 2*HID
#define IMG_H 128
#define IMG_W 128
#define HW    16384    // 128*128

// Scratch u, INTERLEAVED: g_u2[b][cp][px] holds pair (u[cp], u[cp+128]),
// cp in 0..127.  (B, 128, HW, 2) fp32 = 128 MiB device global (no alloc).
__device__ float g_u2[(size_t)BATCH * HID * HW * 2];

// ---------------- packed f32x2 helpers (sm_103a FFMA2) ----------------
__device__ __forceinline__ unsigned long long pk2(float v) {
    unsigned long long r;
    asm("mov.b64 %0, {%1, %1};" : "=l"(r) : "f"(v));
    return r;
}
__device__ __forceinline__ unsigned long long fma2(unsigned long long a,
                                                   unsigned long long b,
                                                   unsigned long long c) {
    unsigned long long d;
    asm("fma.rn.f32x2 %0, %1, %2, %3;" : "=l"(d) : "l"(a), "l"(b), "l"(c));
    return d;
}
__device__ __forceinline__ void upk(unsigned long long v, float& lo, float& hi) {
    asm("mov.b64 {%0, %1}, %2;" : "=f"(lo), "=f"(hi) : "l"(v));
}

// ---------------- cp.async helpers ----------------
__device__ __forceinline__ void cp16(void* smem_dst, const void* gmem_src, int src_sz) {
    unsigned int s = (unsigned int)__cvta_generic_to_shared(smem_dst);
    asm volatile("cp.async.ca.shared.global [%0], [%1], 16, %2;\n"
                 :: "r"(s), "l"(gmem_src), "r"(src_sz));
}
__device__ __forceinline__ void cp_commit() {
    asm volatile("cp.async.commit_group;\n");
}
template <int N>
__device__ __forceinline__ void cp_wait() {
    asm volatile("cp.async.wait_group %0;\n" :: "n"(N));
}

// =====================================================================
// Kernel 1: u[b,o,p] = sum_k W_in[o,k] * x[b,k,p], stored interleaved:
//           g_u2[((b*128+cp)*HW+px)*2 + {0,1}] = (u[cp], u[cp+128])
// CTA: 256 threads (16 tx x 16 ty) covering 64 channel-PAIRS x 128 px.
// Thread tile: 4 pairs (8 channels) x 8 px = 32 FFMA2 per k.
// K=64 split into two 32-deep phases sharing the SMEM buffers.
// Ws2 holds weights pre-duplicated as (w,w) float2 so FFMA2 reads them
// directly (no pk2 in the inner loop).
// =====================================================================
__global__ void __launch_bounds__(256, 2) k_proj_in(const float* __restrict__ x,
                                                    const float* __restrict__ W_in) {
    __shared__ float xs[32 * 128];      // [kk][px]           16384 B
    __shared__ float Ws2[32 * 256];     // [kk][128 float2]   32768 B  (total 48 KB)

    const int t   = threadIdx.x;
    const int b   = blockIdx.z;
    const int cp0 = blockIdx.y * 64;    // channel-pair base (0 or 64)
    const int p0  = blockIdx.x * 128;

    const int tx = t & 15;              // px group
    const int ty = t >> 4;              // pair group (4 pairs)
    const int pb = tx * 8;

    unsigned long long aa[4][4], ab[4][4];   // [pair][px-pair]
#pragma unroll
    for (int i = 0; i < 4; i++)
#pragma unroll
        for (int j = 0; j < 4; j++) { aa[i][j] = 0ull; ab[i][j] = 0ull; }

    const float* xg = x + ((size_t)b * DIM) * HW + p0;

#pragma unroll 1
    for (int ph = 0; ph < 2; ph++) {
        const int k0 = ph * 32;

        // ---- stage xs: 32 ch x 128 px = 1024 16B-chunks, 4/thread ----
#pragma unroll
        for (int i = 0; i < 4; i++) {
            int idx = t + i * 256;            // 0..1023
            int kk  = idx >> 5;
            int c4  = idx & 31;
            cp16(&xs[idx * 4], xg + (size_t)(k0 + kk) * HW + c4 * 4, 16);
        }
        cp_commit();

        // ---- stage Ws2 (duplicated pairs): idx over 1024 float4-ish units ----
        // Each thread loads float4 of W_in (4 consecutive k of one channel),
        // stores 4 duplicated float2.  j<64 -> a-channel cp0+j ; j>=64 -> cp0+j+64.
#pragma unroll
        for (int i = 0; i < 4; i++) {
            int idx = t + i * 256;            // 0..1023
            int j   = idx & 127;              // channel slot
            int kq  = idx >> 7;               // 0..7 (4 k each)
            int ch  = cp0 + j + ((j < 64) ? 0 : 64);
            float4 w = *(const float4*)&W_in[ch * 64 + k0 + kq * 4];
            float2* dst = (float2*)Ws2;       // [kk*128 + j]
            dst[(kq * 4 + 0) * 128 + j] = make_float2(w.x, w.x);
            dst[(kq * 4 + 1) * 128 + j] = make_float2(w.y, w.y);
            dst[(kq * 4 + 2) * 128 + j] = make_float2(w.z, w.z);
            dst[(kq * 4 + 3) * 128 + j] = make_float2(w.w, w.w);
        }
        cp_wait<0>();
        __syncthreads();

        // ---- inner loop: 32 k, 32 FFMA2 each ----
#pragma unroll 8
        for (int kk = 0; kk < 32; kk++) {
            const float* Wr = Ws2 + kk * 256;
            ulonglong2 wa01 = *(const ulonglong2*)(Wr + 8 * ty);
            ulonglong2 wa23 = *(const ulonglong2*)(Wr + 8 * ty + 4);
            ulonglong2 wb01 = *(const ulonglong2*)(Wr + 128 + 8 * ty);
            ulonglong2 wb23 = *(const ulonglong2*)(Wr + 128 + 8 * ty + 4);
            ulonglong2 xv0  = *(const ulonglong2*)(xs + kk * 128 + pb);
            ulonglong2 xv1  = *(const ulonglong2*)(xs + kk * 128 + pb + 4);

            aa[0][0] = fma2(wa01.x, xv0.x, aa[0][0]);
            aa[0][1] = fma2(wa01.x, xv0.y, aa[0][1]);
            aa[0][2] = fma2(wa01.x, xv1.x, aa[0][2]);
            aa[0][3] = fma2(wa01.x, xv1.y, aa[0][3]);
            aa[1][0] = fma2(wa01.y, xv0.x, aa[1][0]);
            aa[1][1] = fma2(wa01.y, xv0.y, aa[1][1]);
            aa[1][2] = fma2(wa01.y, xv1.x, aa[1][2]);
            aa[1][3] = fma2(wa01.y, xv1.y, aa[1][3]);
            aa[2][0] = fma2(wa23.x, xv0.x, aa[2][0]);
            aa[2][1] = fma2(wa23.x, xv0.y, aa[2][1]);
            aa[2][2] = fma2(wa23.x, xv1.x, aa[2][2]);
            aa[2][3] = fma2(wa23.x, xv1.y, aa[2][3]);
            aa[3][0] = fma2(wa23.y, xv0.x, aa[3][0]);
            aa[3][1] = fma2(wa23.y, xv0.y, aa[3][1]);
            aa[3][2] = fma2(wa23.y, xv1.x, aa[3][2]);
            aa[3][3] = fma2(wa23.y, xv1.y, aa[3][3]);

            ab[0][0] = fma2(wb01.x, xv0.x, ab[0][0]);
            ab[0][1] = fma2(wb01.x, xv0.y, ab[0][1]);
            ab[0][2] = fma2(wb01.x, xv1.x, ab[0][2]);
            ab[0][3] = fma2(wb01.x, xv1.y, ab[0][3]);
            ab[1][0] = fma2(wb01.y, xv0.x, ab[1][0]);
            ab[1][1] = fma2(wb01.y, xv0.y, ab[1][1]);
            ab[1][2] = fma2(wb01.y, xv1.x, ab[1][2]);
            ab[1][3] = fma2(wb01.y, xv1.y, ab[1][3]);
            ab[2][0] = fma2(wb23.x, xv0.x, ab[2][0]);
            ab[2][1] = fma2(wb23.x, xv0.y, ab[2][1]);
            ab[2][2] = fma2(wb23.x, xv1.x, ab[2][2]);
            ab[2][3] = fma2(wb23.x, xv1.y, ab[2][3]);
            ab[3][0] = fma2(wb23.y, xv0.x, ab[3][0]);
            ab[3][1] = fma2(wb23.y, xv0.y, ab[3][1]);
            ab[3][2] = fma2(wb23.y, xv1.x, ab[3][2]);
            ab[3][3] = fma2(wb23.y, xv1.y, ab[3][3]);
        }
        if (ph == 0) __syncthreads();   // all reads done before restaging
    }

    // ---- epilogue: interleaved stores (a,b) per pixel ----
#pragma unroll
    for (int ci = 0; ci < 4; ci++) {
        int cp = cp0 + 4 * ty + ci;
        float* base = g_u2 + (((size_t)b * HID + cp) * HW + p0 + pb) * 2;
#pragma unroll
        for (int j = 0; j < 4; j++) {
            float alo, ahi, blo, bhi;
            upk(aa[ci][j], alo, ahi);
            upk(ab[ci][j], blo, bhi);
            float4 v = make_float4(alo, blo, ahi, bhi);
            *(float4*)(base + 4 * j) = v;   // px = pb+2j, pb+2j+1 interleaved
        }
    }
}

// =====================================================================
// Kernel 2: dynamic depthwise 3x3 + exact GELU gate + project_out
// CTA = one image row (batch b, row y), 256 threads.
// Reads interleaved u pairs: conv on BOTH branches via packed FFMA2
// (taps interleaved in kc2).  Halo rows: 256 interior floats (128 px x 2),
// pixel x at smem index 4+2x, row stride HROW2=264, pads zeroed once.
// Then rank-1 GEMM update of the 64x128 output tile (4o x 8px / thread).
// =====================================================================
#define HROW2 264
#define HSZ   (3 * HROW2)           // one buffer = 792 floats

__global__ void __launch_bounds__(256) k_dw_gate_out(const float* __restrict__ genk,
                                                     const float* __restrict__ dwkg,
                                                     const float* __restrict__ lam,
                                                     const float* __restrict__ W_out,
                                                     float* __restrict__ out) {
    __shared__ float kc2[HID * 18];        // [cp][tap][2] interleaved   9216 B
    __shared__ float Wo[HID * 64];         // [c][o]                    32768 B
    __shared__ float halo[2][HSZ];         // double-buffered            6336 B
    __shared__ float gs[128];              //                             512 B

    const int t = threadIdx.x;
    const int b = blockIdx.z;
    const int y = blockIdx.x;              // image row 0..127

    // Zero halos (pads must stay zero: SAME padding)
    for (int i = t; i < 2 * HSZ; i += 256) ((float*)halo)[i] = 0.0f;
    // kc2[cp*18 + tap*2 + br] = dw[c] + lam[c]*gen[b,c],  c = cp + br*128
    for (int idx = t; idx < HID * 18; idx += 256) {
        int cp  = idx / 18;
        int rem = idx - cp * 18;
        int tap = rem >> 1;
        int br  = rem & 1;
        int c   = cp + br * HID;
        kc2[idx] = dwkg[c * 9 + tap] + lam[c] * genk[b * (C2 * 9) + c * 9 + tap];
    }
    // W_out (64,128) -> Wo[c][o]
    for (int idx = t; idx < 64 * HID; idx += 256) {
        int o = idx >> 7, c = idx & 127;
        Wo[c * 64 + o] = W_out[idx];
    }
    __syncthreads();

    // Halo staging: 3 rows x 64 16B-chunks = 192 cp.asyncs, 1/thread.
    // dst offset = r*264 + 4 + 4*ch  (16B aligned).
    const float* Ub = g_u2 + ((size_t)b * HID) * HW * 2;
    auto stage = [&](int cp, int buf) {
        if (t < 192) {
            int r  = t >> 6;
            int ch = t & 63;
            int gy = y + r - 1;
            bool ok = (unsigned)gy < 128u;
            int gyc = ok ? gy : 0;
            const float* src = Ub + ((size_t)cp * HW + gyc * IMG_W) * 2 + ch * 4;
            float* dst = &halo[buf][r * HROW2 + 4 + ch * 4];
            cp16(dst, src, ok ? 16 : 0);   // src_sz=0 zero-fills (SAME pad)
        }
        cp_commit();
    };

    stage(0, 0);   // prologue prefetch

    const int tp = t & 15;        // px group
    const int to = t >> 4;        // o group 0..15
    const int ob = to * 4;
    const int pb = tp * 8;

    unsigned long long acc[16];
#pragma unroll
    for (int j = 0; j < 16; j++) acc[j] = 0ull;

    for (int cp = 0; cp < HID; cp++) {
        int nc = cp + 1;
        if (nc < HID) stage(nc, nc & 1);
        else cp_commit();          // keep group accounting uniform
        cp_wait<1>();              // channel cp's halos complete
        __syncthreads();           // (S1) halos visible; protects gs

        // ---- packed conv (both branches) + exact-GELU gate ----
        if (t < 128) {
            const float* H = &halo[cp & 1][0];
            const float* K2v = &kc2[cp * 18];
            unsigned long long v2 = 0ull;
#pragma unroll
            for (int r = 0; r < 3; r++) {
#pragma unroll
                for (int dx = 0; dx < 3; dx++) {
                    unsigned long long uv =
                        *(const unsigned long long*)&H[r * HROW2 + 2 * t + 2 * dx + 2];
                    unsigned long long tap =
                        *(const unsigned long long*)&K2v[(r * 3 + dx) * 2];
                    v2 = fma2(tap, uv, v2);
                }
            }
            float va, vb;
            upk(v2, va, vb);
            gs[t] = 0.5f * va * (1.0f + erff(va * 0.7071067811865476f)) * vb;
        }
        __syncthreads();           // (S2) gs visible

        // ---- rank-1 GEMM update: acc[o][px] += Wo[cp][o] * gs[px] ----
        float4 w = *(const float4*)&Wo[cp * 64 + ob];
        unsigned long long wp0 = pk2(w.x), wp1 = pk2(w.y),
                           wp2 = pk2(w.z), wp3 = pk2(w.w);
        const ulonglong2* gp = (const ulonglong2*)&gs[pb];
        ulonglong2 g0 = gp[0], g1 = gp[1];
        acc[0]  = fma2(wp0, g0.x, acc[0]);
        acc[1]  = fma2(wp0, g0.y, acc[1]);
        acc[2]  = fma2(wp0, g1.x, acc[2]);
        acc[3]  = fma2(wp0, g1.y, acc[3]);
        acc[4]  = fma2(wp1, g0.x, acc[4]);
        acc[5]  = fma2(wp1, g0.y, acc[5]);
        acc[6]  = fma2(wp1, g1.x, acc[6]);
        acc[7]  = fma2(wp1, g1.y, acc[7]);
        acc[8]  = fma2(wp2, g0.x, acc[8]);
        acc[9]  = fma2(wp2, g0.y, acc[9]);
        acc[10] = fma2(wp2, g1.x, acc[10]);
        acc[11] = fma2(wp2, g1.y, acc[11]);
        acc[12] = fma2(wp3, g0.x, acc[12]);
        acc[13] = fma2(wp3, g0.y, acc[13]);
        acc[14] = fma2(wp3, g1.x, acc[14]);
        acc[15] = fma2(wp3, g1.y, acc[15]);
    }

    // Epilogue: thread owns 4 o-rows x 8 px of row y
#pragma unroll
    for (int oi = 0; oi < 4; oi++) {
        float* dst = out + ((size_t)b * DIM + (ob + oi)) * HW + y * IMG_W + pb;
        ulonglong2 v0, v1;
        v0.x = acc[oi * 4 + 0]; v0.y = acc[oi * 4 + 1];
        v1.x = acc[oi * 4 + 2]; v1.y = acc[oi * 4 + 3];
        ((ulonglong2*)dst)[0] = v0;
        ((ulonglong2*)dst)[1] = v1;
    }
}

// =====================================================================
// Launch (graph-capturable, no allocs)
// Inputs: x, gen_kernel, W_in, dw_kernel, lambda_dw, W_out
// =====================================================================
extern "C" void kernel_launch(void* const* d_in, const int* in_sizes, int n_in,
                              void* d_out, int out_size) {
    const float* x     = (const float*)d_in[0];
    const float* genk  = (const float*)d_in[1];
    const float* W_in  = (const float*)d_in[2];
    const float* dwk   = (const float*)d_in[3];
    const float* lam   = (const float*)d_in[4];
    const float* W_out = (const float*)d_in[5];
    float* out = (float*)d_out;

    dim3 g1(HW / 128, HID / 64, BATCH);     // (128, 2, 8)
    k_proj_in<<<g1, 256>>>(x, W_in);

    dim3 g2(IMG_H, 1, BATCH);               // one CTA per image row
    k_dw_gate_out<<<g2, 256>>>(genk, dwk, lam, W_out, out);
}

// round 9
// speedup vs baseline: 2.1148x; 1.1286x over previous
#include <cuda_runtime.h>
#include <math.h>

// Problem constants
#define BATCH 8
#define DIM   64
#define HID   128
#define C2    256      // 2*HID
#define IMG_H 128
#define IMG_W 128
#define HW    16384    // 128*128

// Scratch u, INTERLEAVED: g_u2[b][cp][px] holds pair (u[cp], u[cp+128]),
// cp in 0..127.  (B, 128, HW, 2) fp32 = 128 MiB device global (no alloc).
__device__ float g_u2[(size_t)BATCH * HID * HW * 2];
// Scratch g = gelu(x1)*x2, planar (B, HID, HW) fp32 = 64 MiB.
__device__ float g_g[(size_t)BATCH * HID * HW];

// ---------------- packed f32x2 helpers (sm_103a FFMA2) ----------------
__device__ __forceinline__ unsigned long long pk2(float v) {
    unsigned long long r;
    asm("mov.b64 %0, {%1, %1};" : "=l"(r) : "f"(v));
    return r;
}
__device__ __forceinline__ unsigned long long fma2(unsigned long long a,
                                                   unsigned long long b,
                                                   unsigned long long c) {
    unsigned long long d;
    asm("fma.rn.f32x2 %0, %1, %2, %3;" : "=l"(d) : "l"(a), "l"(b), "l"(c));
    return d;
}
__device__ __forceinline__ void upk(unsigned long long v, float& lo, float& hi) {
    asm("mov.b64 {%0, %1}, %2;" : "=f"(lo), "=f"(hi) : "l"(v));
}

// ---------------- cp.async helpers ----------------
__device__ __forceinline__ void cp16(void* smem_dst, const void* gmem_src, int src_sz) {
    unsigned int s = (unsigned int)__cvta_generic_to_shared(smem_dst);
    asm volatile("cp.async.ca.shared.global [%0], [%1], 16, %2;\n"
                 :: "r"(s), "l"(gmem_src), "r"(src_sz));
}
__device__ __forceinline__ void cp_commit() {
    asm volatile("cp.async.commit_group;\n");
}
template <int N>
__device__ __forceinline__ void cp_wait() {
    asm volatile("cp.async.wait_group %0;\n" :: "n"(N));
}

// =====================================================================
// Kernel 1: u[b,o,p] = sum_k W_in[o,k] * x[b,k,p], stored interleaved
// (unchanged from round 7; ~133 us, proven)
// =====================================================================
__global__ void __launch_bounds__(256, 2) k_proj_in(const float* __restrict__ x,
                                                    const float* __restrict__ W_in) {
    __shared__ float xs[32 * 128];      // [kk][px]           16384 B
    __shared__ float Ws2[32 * 256];     // [kk][128 float2]   32768 B

    const int t   = threadIdx.x;
    const int b   = blockIdx.z;
    const int cp0 = blockIdx.y * 64;
    const int p0  = blockIdx.x * 128;

    const int tx = t & 15;
    const int ty = t >> 4;
    const int pb = tx * 8;

    unsigned long long aa[4][4], ab[4][4];
#pragma unroll
    for (int i = 0; i < 4; i++)
#pragma unroll
        for (int j = 0; j < 4; j++) { aa[i][j] = 0ull; ab[i][j] = 0ull; }

    const float* xg = x + ((size_t)b * DIM) * HW + p0;

#pragma unroll 1
    for (int ph = 0; ph < 2; ph++) {
        const int k0 = ph * 32;
#pragma unroll
        for (int i = 0; i < 4; i++) {
            int idx = t + i * 256;
            int kk  = idx >> 5;
            int c4  = idx & 31;
            cp16(&xs[idx * 4], xg + (size_t)(k0 + kk) * HW + c4 * 4, 16);
        }
        cp_commit();
#pragma unroll
        for (int i = 0; i < 4; i++) {
            int idx = t + i * 256;
            int j   = idx & 127;
            int kq  = idx >> 7;
            int ch  = cp0 + j + ((j < 64) ? 0 : 64);
            float4 w = *(const float4*)&W_in[ch * 64 + k0 + kq * 4];
            float2* dst = (float2*)Ws2;
            dst[(kq * 4 + 0) * 128 + j] = make_float2(w.x, w.x);
            dst[(kq * 4 + 1) * 128 + j] = make_float2(w.y, w.y);
            dst[(kq * 4 + 2) * 128 + j] = make_float2(w.z, w.z);
            dst[(kq * 4 + 3) * 128 + j] = make_float2(w.w, w.w);
        }
        cp_wait<0>();
        __syncthreads();

#pragma unroll 8
        for (int kk = 0; kk < 32; kk++) {
            const float* Wr = Ws2 + kk * 256;
            ulonglong2 wa01 = *(const ulonglong2*)(Wr + 8 * ty);
            ulonglong2 wa23 = *(const ulonglong2*)(Wr + 8 * ty + 4);
            ulonglong2 wb01 = *(const ulonglong2*)(Wr + 128 + 8 * ty);
            ulonglong2 wb23 = *(const ulonglong2*)(Wr + 128 + 8 * ty + 4);
            ulonglong2 xv0  = *(const ulonglong2*)(xs + kk * 128 + pb);
            ulonglong2 xv1  = *(const ulonglong2*)(xs + kk * 128 + pb + 4);

            aa[0][0] = fma2(wa01.x, xv0.x, aa[0][0]);
            aa[0][1] = fma2(wa01.x, xv0.y, aa[0][1]);
            aa[0][2] = fma2(wa01.x, xv1.x, aa[0][2]);
            aa[0][3] = fma2(wa01.x, xv1.y, aa[0][3]);
            aa[1][0] = fma2(wa01.y, xv0.x, aa[1][0]);
            aa[1][1] = fma2(wa01.y, xv0.y, aa[1][1]);
            aa[1][2] = fma2(wa01.y, xv1.x, aa[1][2]);
            aa[1][3] = fma2(wa01.y, xv1.y, aa[1][3]);
            aa[2][0] = fma2(wa23.x, xv0.x, aa[2][0]);
            aa[2][1] = fma2(wa23.x, xv0.y, aa[2][1]);
            aa[2][2] = fma2(wa23.x, xv1.x, aa[2][2]);
            aa[2][3] = fma2(wa23.x, xv1.y, aa[2][3]);
            aa[3][0] = fma2(wa23.y, xv0.x, aa[3][0]);
            aa[3][1] = fma2(wa23.y, xv0.y, aa[3][1]);
            aa[3][2] = fma2(wa23.y, xv1.x, aa[3][2]);
            aa[3][3] = fma2(wa23.y, xv1.y, aa[3][3]);

            ab[0][0] = fma2(wb01.x, xv0.x, ab[0][0]);
            ab[0][1] = fma2(wb01.x, xv0.y, ab[0][1]);
            ab[0][2] = fma2(wb01.x, xv1.x, ab[0][2]);
            ab[0][3] = fma2(wb01.x, xv1.y, ab[0][3]);
            ab[1][0] = fma2(wb01.y, xv0.x, ab[1][0]);
            ab[1][1] = fma2(wb01.y, xv0.y, ab[1][1]);
            ab[1][2] = fma2(wb01.y, xv1.x, ab[1][2]);
            ab[1][3] = fma2(wb01.y, xv1.y, ab[1][3]);
            ab[2][0] = fma2(wb23.x, xv0.x, ab[2][0]);
            ab[2][1] = fma2(wb23.x, xv0.y, ab[2][1]);
            ab[2][2] = fma2(wb23.x, xv1.x, ab[2][2]);
            ab[2][3] = fma2(wb23.x, xv1.y, ab[2][3]);
            ab[3][0] = fma2(wb23.y, xv0.x, ab[3][0]);
            ab[3][1] = fma2(wb23.y, xv0.y, ab[3][1]);
            ab[3][2] = fma2(wb23.y, xv1.x, ab[3][2]);
            ab[3][3] = fma2(wb23.y, xv1.y, ab[3][3]);
        }
        if (ph == 0) __syncthreads();
    }

#pragma unroll
    for (int ci = 0; ci < 4; ci++) {
        int cp = cp0 + 4 * ty + ci;
        float* base = g_u2 + (((size_t)b * HID + cp) * HW + p0 + pb) * 2;
#pragma unroll
        for (int j = 0; j < 4; j++) {
            float alo, ahi, blo, bhi;
            upk(aa[ci][j], alo, ahi);
            upk(ab[ci][j], blo, bhi);
            *(float4*)(base + 4 * j) = make_float4(alo, blo, ahi, bhi);
        }
    }
}

// =====================================================================
// Kernel 2a: dynamic depthwise 3x3 + exact GELU gate -> g (planar).
// CTA = one (batch, channel-pair, 32-row block). Stage the 34-row
// interleaved halo ONCE; taps live in registers. Each thread computes
// two 8-px strips via 6 aligned LDS.128 per row, writes 2x STG.128.
// Halo row: pair px x at floats [4+2x, 5+2x]; pads px {-2,-1,128,129}
// at floats 0..3 / 260..263; row stride 264.
// =====================================================================
#define AROW 264
__global__ void __launch_bounds__(256) k_conv_gelu(const float* __restrict__ genk,
                                                   const float* __restrict__ dwkg,
                                                   const float* __restrict__ lam) {
    __shared__ float halo[34 * AROW];     // 35904 B
    __shared__ float kc2s[18];

    const int t  = threadIdx.x;
    const int cp = blockIdx.x;            // channel pair 0..127
    const int rb = blockIdx.y;            // row block 0..3
    const int b  = blockIdx.z;
    const int y0 = rb * 32;

    // taps: kc2s[tap*2+br] = dw[c] + lam[c]*gen[b,c], c = cp + br*128
    if (t < 18) {
        int tap = t >> 1, br = t & 1;
        int c = cp + br * HID;
        kc2s[tap * 2 + br] = dwkg[c * 9 + tap] + lam[c] * genk[b * (C2 * 9) + c * 9 + tap];
    }
    // zero pad columns (floats 0..3 and 260..263 of each of 34 rows)
    // NOTE: strided loop — 272 items > 256 threads (round-8 bug was `if (t<272)`)
    for (int i = t; i < 272; i += 256) {
        int rr = i >> 3, j = i & 7;
        halo[rr * AROW + ((j < 4) ? j : (256 + j))] = 0.0f;
    }
    // stage 34 rows x 64 16B-chunks = 2176 cp.asyncs
    {
        const float* src0 = g_u2 + ((size_t)b * HID + cp) * HW * 2;
#pragma unroll
        for (int i = 0; i < 9; i++) {
            int idx = t + i * 256;
            if (idx < 2176) {
                int rr = idx >> 6, ch = idx & 63;
                int gy = y0 - 1 + rr;
                bool ok = (unsigned)gy < 128u;
                cp16(&halo[rr * AROW + 4 + ch * 4],
                     src0 + (size_t)(ok ? gy : 0) * 256 + ch * 4, ok ? 16 : 0);
            }
        }
        cp_commit();
    }
    cp_wait<0>();
    __syncthreads();

    unsigned long long tap[9];
#pragma unroll
    for (int i = 0; i < 9; i++) tap[i] = *(const unsigned long long*)&kc2s[2 * i];

    const int s  = t & 15;                // strip 0..15
    const int x0 = s * 8;
    const int yb = t >> 4;                // 0..15
    float* gbase = g_g + ((size_t)b * HID + cp) * HW;

#pragma unroll
    for (int half = 0; half < 2; half++) {
        int y = yb + half * 16;           // local row 0..31
        unsigned long long v[8];
#pragma unroll
        for (int j = 0; j < 8; j++) v[j] = 0ull;

#pragma unroll
        for (int r = 0; r < 3; r++) {
            // pairs px x0-2 .. x0+9 : floats [2*x0 .. 2*x0+47], 16B aligned
            const ulonglong2* Hrow = (const ulonglong2*)&halo[(y + r) * AROW + 2 * x0];
            ulonglong2 q0 = Hrow[0], q1 = Hrow[1], q2 = Hrow[2],
                       q3 = Hrow[3], q4 = Hrow[4], q5 = Hrow[5];
            unsigned long long p[12] = {q0.x, q0.y, q1.x, q1.y, q2.x, q2.y,
                                        q3.x, q3.y, q4.x, q4.y, q5.x, q5.y};
#pragma unroll
            for (int dx = 0; dx < 3; dx++) {
                unsigned long long tp_ = tap[r * 3 + dx];
#pragma unroll
                for (int j = 0; j < 8; j++)
                    v[j] = fma2(tp_, p[j + dx + 1], v[j]);
            }
        }
        float o8[8];
#pragma unroll
        for (int j = 0; j < 8; j++) {
            float va, vb;
            upk(v[j], va, vb);
            o8[j] = 0.5f * va * (1.0f + erff(va * 0.7071067811865476f)) * vb;
        }
        float* dst = gbase + (y0 + y) * IMG_W + x0;
        *(float4*)dst       = make_float4(o8[0], o8[1], o8[2], o8[3]);
        *(float4*)(dst + 4) = make_float4(o8[4], o8[5], o8[6], o8[7]);
    }
}

// =====================================================================
// Kernel 2b: out[b,o,p] = sum_c W_out[o,c] * g[b,c,p]
// CTA: 64 o x 256 px, 256 threads, thread tile 8o x 8px (32 packed acc).
// K=128 in 4 phases of 32; weights duplicated (w,w) in smem.
// =====================================================================
__global__ void __launch_bounds__(256, 2) k_proj_out(const float* __restrict__ W_out,
                                                     float* __restrict__ out) {
    __shared__ float gsT[32 * 256];     // [kk][px]         32768 B
    __shared__ float Wo2[32 * 128];     // [kk][64 o dup]   16384 B

    const int t  = threadIdx.x;
    const int b  = blockIdx.z;
    const int p0 = blockIdx.x * 256;

    const int tx = t & 31;              // px group
    const int ty = t >> 5;              // o group 0..7
    const int pb = tx * 8;
    const int ob = ty * 8;

    unsigned long long acc[8][4];
#pragma unroll
    for (int i = 0; i < 8; i++)
#pragma unroll
        for (int j = 0; j < 4; j++) acc[i][j] = 0ull;

    const float* gb = g_g + ((size_t)b * HID) * HW;

#pragma unroll 1
    for (int ph = 0; ph < 4; ph++) {
        const int c0 = ph * 32;
        // stage g tile: 32 ch x 64 chunks = 2048, 8/thread
#pragma unroll
        for (int i = 0; i < 8; i++) {
            int idx = t + i * 256;
            int kk = idx >> 6, ch = idx & 63;
            cp16(&gsT[idx * 4], gb + (size_t)(c0 + kk) * HW + p0 + ch * 4, 16);
        }
        cp_commit();
        // stage duplicated weights: 32 kk x 64 o
#pragma unroll
        for (int i = 0; i < 8; i++) {
            int idx = t + i * 256;
            int kk = idx >> 6, o = idx & 63;
            float w = W_out[o * HID + c0 + kk];
            *(float2*)&Wo2[kk * 128 + o * 2] = make_float2(w, w);
        }
        cp_wait<0>();
        __syncthreads();

#pragma unroll 8
        for (int kk = 0; kk < 32; kk++) {
            const ulonglong2* Wr = (const ulonglong2*)&Wo2[kk * 128 + ob * 2];
            ulonglong2 w01 = Wr[0], w23 = Wr[1], w45 = Wr[2], w67 = Wr[3];
            const ulonglong2* gp = (const ulonglong2*)&gsT[kk * 256 + pb];
            ulonglong2 gA = gp[0], gB = gp[1];

            acc[0][0] = fma2(w01.x, gA.x, acc[0][0]);
            acc[0][1] = fma2(w01.x, gA.y, acc[0][1]);
            acc[0][2] = fma2(w01.x, gB.x, acc[0][2]);
            acc[0][3] = fma2(w01.x, gB.y, acc[0][3]);
            acc[1][0] = fma2(w01.y, gA.x, acc[1][0]);
            acc[1][1] = fma2(w01.y, gA.y, acc[1][1]);
            acc[1][2] = fma2(w01.y, gB.x, acc[1][2]);
            acc[1][3] = fma2(w01.y, gB.y, acc[1][3]);
            acc[2][0] = fma2(w23.x, gA.x, acc[2][0]);
            acc[2][1] = fma2(w23.x, gA.y, acc[2][1]);
            acc[2][2] = fma2(w23.x, gB.x, acc[2][2]);
            acc[2][3] = fma2(w23.x, gB.y, acc[2][3]);
            acc[3][0] = fma2(w23.y, gA.x, acc[3][0]);
            acc[3][1] = fma2(w23.y, gA.y, acc[3][1]);
            acc[3][2] = fma2(w23.y, gB.x, acc[3][2]);
            acc[3][3] = fma2(w23.y, gB.y, acc[3][3]);
            acc[4][0] = fma2(w45.x, gA.x, acc[4][0]);
            acc[4][1] = fma2(w45.x, gA.y, acc[4][1]);
            acc[4][2] = fma2(w45.x, gB.x, acc[4][2]);
            acc[4][3] = fma2(w45.x, gB.y, acc[4][3]);
            acc[5][0] = fma2(w45.y, gA.x, acc[5][0]);
            acc[5][1] = fma2(w45.y, gA.y, acc[5][1]);
            acc[5][2] = fma2(w45.y, gB.x, acc[5][2]);
            acc[5][3] = fma2(w45.y, gB.y, acc[5][3]);
            acc[6][0] = fma2(w67.x, gA.x, acc[6][0]);
            acc[6][1] = fma2(w67.x, gA.y, acc[6][1]);
            acc[6][2] = fma2(w67.x, gB.x, acc[6][2]);
            acc[6][3] = fma2(w67.x, gB.y, acc[6][3]);
            acc[7][0] = fma2(w67.y, gA.x, acc[7][0]);
            acc[7][1] = fma2(w67.y, gA.y, acc[7][1]);
            acc[7][2] = fma2(w67.y, gB.x, acc[7][2]);
            acc[7][3] = fma2(w67.y, gB.y, acc[7][3]);
        }
        if (ph < 3) __syncthreads();
    }

    // Epilogue: 8 o-rows x 8 px
#pragma unroll
    for (int oi = 0; oi < 8; oi++) {
        float* dst = out + ((size_t)b * DIM + (ob + oi)) * HW + p0 + pb;
        ulonglong2 v0, v1;
        v0.x = acc[oi][0]; v0.y = acc[oi][1];
        v1.x = acc[oi][2]; v1.y = acc[oi][3];
        ((ulonglong2*)dst)[0] = v0;
        ((ulonglong2*)dst)[1] = v1;
    }
}

// =====================================================================
// Launch (graph-capturable, no allocs)
// Inputs: x, gen_kernel, W_in, dw_kernel, lambda_dw, W_out
// =====================================================================
extern "C" void kernel_launch(void* const* d_in, const int* in_sizes, int n_in,
                              void* d_out, int out_size) {
    const float* x     = (const float*)d_in[0];
    const float* genk  = (const float*)d_in[1];
    const float* W_in  = (const float*)d_in[2];
    const float* dwk   = (const float*)d_in[3];
    const float* lam   = (const float*)d_in[4];
    const float* W_out = (const float*)d_in[5];
    float* out = (float*)d_out;

    dim3 g1(HW / 128, HID / 64, BATCH);     // (128, 2, 8)
    k_proj_in<<<g1, 256>>>(x, W_in);

    dim3 g2(HID, IMG_H / 32, BATCH);        // (128, 4, 8)
    k_conv_gelu<<<g2, 256>>>(genk, dwk, lam);

    dim3 g3(HW / 256, 1, BATCH);            // (64, 1, 8)
    k_proj_out<<<g3, 256>>>(W_out, out);
}

// round 10
// speedup vs baseline: 2.4693x; 1.1676x over previous
#include <cuda_runtime.h>
#include <math.h>

// Problem constants
#define BATCH 8
#define DIM   64
#define HID   128
#define C2    256      // 2*HID
#define IMG_H 128
#define IMG_W 128
#define HW    16384    // 128*128

// Scratch u, INTERLEAVED: g_u2[b][cp][px] holds pair (u[cp], u[cp+128]),
// cp in 0..127.  (B, 128, HW, 2) fp32 = 128 MiB device global (no alloc).
__device__ float g_u2[(size_t)BATCH * HID * HW * 2];
// Scratch g = gelu(x1)*x2, planar (B, HID, HW) fp32 = 64 MiB.
__device__ float g_g[(size_t)BATCH * HID * HW];

// ---------------- packed f32x2 helpers (sm_103a FFMA2) ----------------
__device__ __forceinline__ unsigned long long pk2(float v) {
    unsigned long long r;
    asm("mov.b64 %0, {%1, %1};" : "=l"(r) : "f"(v));
    return r;
}
__device__ __forceinline__ unsigned long long fma2(unsigned long long a,
                                                   unsigned long long b,
                                                   unsigned long long c) {
    unsigned long long d;
    asm("fma.rn.f32x2 %0, %1, %2, %3;" : "=l"(d) : "l"(a), "l"(b), "l"(c));
    return d;
}
__device__ __forceinline__ void upk(unsigned long long v, float& lo, float& hi) {
    asm("mov.b64 {%0, %1}, %2;" : "=f"(lo), "=f"(hi) : "l"(v));
}

// ---------------- cp.async helpers ----------------
__device__ __forceinline__ void cp16(void* smem_dst, const void* gmem_src, int src_sz) {
    unsigned int s = (unsigned int)__cvta_generic_to_shared(smem_dst);
    asm volatile("cp.async.ca.shared.global [%0], [%1], 16, %2;\n"
                 :: "r"(s), "l"(gmem_src), "r"(src_sz));
}
__device__ __forceinline__ void cp_commit() {
    asm volatile("cp.async.commit_group;\n");
}
template <int N>
__device__ __forceinline__ void cp_wait() {
    asm volatile("cp.async.wait_group %0;\n" :: "n"(N));
}

// 16B-chunk XOR swizzles (conflict-free stride-32B/64B access)
__device__ __forceinline__ int swz4(int c) { return c ^ ((c >> 3) & 3); }  // 512B row
__device__ __forceinline__ int swz8(int c) { return c ^ ((c >> 3) & 7); }  // 1024B+ row

// =====================================================================
// Kernel 1: u[b,o,p] = sum_k W_in[o,k] * x[b,k,p], stored interleaved.
// xs rows (512B) chunk-swizzled: x loads conflict-free.
// =====================================================================
__global__ void __launch_bounds__(256, 2) k_proj_in(const float* __restrict__ x,
                                                    const float* __restrict__ W_in) {
    __shared__ float xs[32 * 128];      // [kk][px swizzled]  16384 B
    __shared__ float Ws2[32 * 256];     // [kk][128 float2]   32768 B

    const int t   = threadIdx.x;
    const int b   = blockIdx.z;
    const int cp0 = blockIdx.y * 64;
    const int p0  = blockIdx.x * 128;

    const int tx = t & 15;
    const int ty = t >> 4;
    const int pb = tx * 8;
    // hoisted swizzled float offsets of this thread's two x chunks
    const int q0 = swz4(2 * tx) * 4;
    const int q1 = swz4(2 * tx + 1) * 4;

    unsigned long long aa[4][4], ab[4][4];
#pragma unroll
    for (int i = 0; i < 4; i++)
#pragma unroll
        for (int j = 0; j < 4; j++) { aa[i][j] = 0ull; ab[i][j] = 0ull; }

    const float* xg = x + ((size_t)b * DIM) * HW + p0;

#pragma unroll 1
    for (int ph = 0; ph < 2; ph++) {
        const int k0 = ph * 32;
#pragma unroll
        for (int i = 0; i < 4; i++) {
            int idx = t + i * 256;
            int kk  = idx >> 5;
            int c4  = idx & 31;
            cp16(&xs[(kk * 32 + swz4(c4)) * 4],
                 xg + (size_t)(k0 + kk) * HW + c4 * 4, 16);
        }
        cp_commit();
#pragma unroll
        for (int i = 0; i < 4; i++) {
            int idx = t + i * 256;
            int j   = idx & 127;
            int kq  = idx >> 7;
            int ch  = cp0 + j + ((j < 64) ? 0 : 64);
            float4 w = *(const float4*)&W_in[ch * 64 + k0 + kq * 4];
            float2* dst = (float2*)Ws2;
            dst[(kq * 4 + 0) * 128 + j] = make_float2(w.x, w.x);
            dst[(kq * 4 + 1) * 128 + j] = make_float2(w.y, w.y);
            dst[(kq * 4 + 2) * 128 + j] = make_float2(w.z, w.z);
            dst[(kq * 4 + 3) * 128 + j] = make_float2(w.w, w.w);
        }
        cp_wait<0>();
        __syncthreads();

#pragma unroll 8
        for (int kk = 0; kk < 32; kk++) {
            const float* Wr = Ws2 + kk * 256;
            ulonglong2 wa01 = *(const ulonglong2*)(Wr + 8 * ty);
            ulonglong2 wa23 = *(const ulonglong2*)(Wr + 8 * ty + 4);
            ulonglong2 wb01 = *(const ulonglong2*)(Wr + 128 + 8 * ty);
            ulonglong2 wb23 = *(const ulonglong2*)(Wr + 128 + 8 * ty + 4);
            ulonglong2 xv0  = *(const ulonglong2*)(xs + kk * 128 + q0);
            ulonglong2 xv1  = *(const ulonglong2*)(xs + kk * 128 + q1);

            aa[0][0] = fma2(wa01.x, xv0.x, aa[0][0]);
            aa[0][1] = fma2(wa01.x, xv0.y, aa[0][1]);
            aa[0][2] = fma2(wa01.x, xv1.x, aa[0][2]);
            aa[0][3] = fma2(wa01.x, xv1.y, aa[0][3]);
            aa[1][0] = fma2(wa01.y, xv0.x, aa[1][0]);
            aa[1][1] = fma2(wa01.y, xv0.y, aa[1][1]);
            aa[1][2] = fma2(wa01.y, xv1.x, aa[1][2]);
            aa[1][3] = fma2(wa01.y, xv1.y, aa[1][3]);
            aa[2][0] = fma2(wa23.x, xv0.x, aa[2][0]);
            aa[2][1] = fma2(wa23.x, xv0.y, aa[2][1]);
            aa[2][2] = fma2(wa23.x, xv1.x, aa[2][2]);
            aa[2][3] = fma2(wa23.x, xv1.y, aa[2][3]);
            aa[3][0] = fma2(wa23.y, xv0.x, aa[3][0]);
            aa[3][1] = fma2(wa23.y, xv0.y, aa[3][1]);
            aa[3][2] = fma2(wa23.y, xv1.x, aa[3][2]);
            aa[3][3] = fma2(wa23.y, xv1.y, aa[3][3]);

            ab[0][0] = fma2(wb01.x, xv0.x, ab[0][0]);
            ab[0][1] = fma2(wb01.x, xv0.y, ab[0][1]);
            ab[0][2] = fma2(wb01.x, xv1.x, ab[0][2]);
            ab[0][3] = fma2(wb01.x, xv1.y, ab[0][3]);
            ab[1][0] = fma2(wb01.y, xv0.x, ab[1][0]);
            ab[1][1] = fma2(wb01.y, xv0.y, ab[1][1]);
            ab[1][2] = fma2(wb01.y, xv1.x, ab[1][2]);
            ab[1][3] = fma2(wb01.y, xv1.y, ab[1][3]);
            ab[2][0] = fma2(wb23.x, xv0.x, ab[2][0]);
            ab[2][1] = fma2(wb23.x, xv0.y, ab[2][1]);
            ab[2][2] = fma2(wb23.x, xv1.x, ab[2][2]);
            ab[2][3] = fma2(wb23.x, xv1.y, ab[2][3]);
            ab[3][0] = fma2(wb23.y, xv0.x, ab[3][0]);
            ab[3][1] = fma2(wb23.y, xv0.y, ab[3][1]);
            ab[3][2] = fma2(wb23.y, xv1.x, ab[3][2]);
            ab[3][3] = fma2(wb23.y, xv1.y, ab[3][3]);
        }
        if (ph == 0) __syncthreads();
    }

#pragma unroll
    for (int ci = 0; ci < 4; ci++) {
        int cp = cp0 + 4 * ty + ci;
        float* base = g_u2 + (((size_t)b * HID + cp) * HW + p0 + pb) * 2;
#pragma unroll
        for (int j = 0; j < 4; j++) {
            float alo, ahi, blo, bhi;
            upk(aa[ci][j], alo, ahi);
            upk(ab[ci][j], blo, bhi);
            *(float4*)(base + 4 * j) = make_float4(alo, blo, ahi, bhi);
        }
    }
}

// =====================================================================
// Kernel 2a: dynamic depthwise 3x3 + exact GELU gate -> g (planar).
// Halo rows chunk-swizzled (interior chunk c=1+ch -> swz8(c)); pad
// chunks 0 and 65 are fixed points of the swizzle, so SAME-padding
// zero-fill is unchanged. Conv reads 6 swizzled 16B chunks per row
// (was 4-way conflicted at 64B stride; now conflict-free).
// =====================================================================
#define AROW 264
__global__ void __launch_bounds__(256) k_conv_gelu(const float* __restrict__ genk,
                                                   const float* __restrict__ dwkg,
                                                   const float* __restrict__ lam) {
    __shared__ float halo[34 * AROW];     // 35904 B
    __shared__ float kc2s[18];

    const int t  = threadIdx.x;
    const int cp = blockIdx.x;            // channel pair 0..127
    const int rb = blockIdx.y;            // row block 0..3
    const int b  = blockIdx.z;
    const int y0 = rb * 32;

    // taps: kc2s[tap*2+br] = dw[c] + lam[c]*gen[b,c], c = cp + br*128
    if (t < 18) {
        int tap = t >> 1, br = t & 1;
        int c = cp + br * HID;
        kc2s[tap * 2 + br] = dwkg[c * 9 + tap] + lam[c] * genk[b * (C2 * 9) + c * 9 + tap];
    }
    // zero pad chunks 0 (floats 0..3) and 65 (floats 260..263) of all 34 rows
    for (int i = t; i < 272; i += 256) {
        int rr = i >> 3, j = i & 7;
        halo[rr * AROW + ((j < 4) ? j : (256 + j))] = 0.0f;
    }
    // stage 34 rows x 64 16B-chunks = 2176 cp.asyncs (swizzled dst)
    {
        const float* src0 = g_u2 + ((size_t)b * HID + cp) * HW * 2;
#pragma unroll
        for (int i = 0; i < 9; i++) {
            int idx = t + i * 256;
            if (idx < 2176) {
                int rr = idx >> 6, ch = idx & 63;
                int gy = y0 - 1 + rr;
                bool ok = (unsigned)gy < 128u;
                cp16(&halo[rr * AROW + swz8(1 + ch) * 4],
                     src0 + (size_t)(ok ? gy : 0) * 256 + ch * 4, ok ? 16 : 0);
            }
        }
        cp_commit();
    }
    cp_wait<0>();
    __syncthreads();

    unsigned long long tap[9];
#pragma unroll
    for (int i = 0; i < 9; i++) tap[i] = *(const unsigned long long*)&kc2s[2 * i];

    const int s  = t & 15;                // strip 0..15
    const int x0 = s * 8;
    const int yb = t >> 4;                // 0..15
    // hoisted swizzled float offsets of the 6 chunks this thread reads per row
    int qof[6];
#pragma unroll
    for (int j = 0; j < 6; j++) qof[j] = swz8(4 * s + j) * 4;

    float* gbase = g_g + ((size_t)b * HID + cp) * HW;

#pragma unroll
    for (int half = 0; half < 2; half++) {
        int y = yb + half * 16;           // local row 0..31
        unsigned long long v[8];
#pragma unroll
        for (int j = 0; j < 8; j++) v[j] = 0ull;

#pragma unroll
        for (int r = 0; r < 3; r++) {
            const float* Hrow = &halo[(y + r) * AROW];
            unsigned long long p[12];
#pragma unroll
            for (int j = 0; j < 6; j++) {
                ulonglong2 qq = *(const ulonglong2*)&Hrow[qof[j]];
                p[2 * j]     = qq.x;
                p[2 * j + 1] = qq.y;
            }
#pragma unroll
            for (int dx = 0; dx < 3; dx++) {
                unsigned long long tp_ = tap[r * 3 + dx];
#pragma unroll
                for (int j = 0; j < 8; j++)
                    v[j] = fma2(tp_, p[j + dx + 1], v[j]);
            }
        }
        float o8[8];
#pragma unroll
        for (int j = 0; j < 8; j++) {
            float va, vb;
            upk(v[j], va, vb);
            o8[j] = 0.5f * va * (1.0f + erff(va * 0.7071067811865476f)) * vb;
        }
        float* dst = gbase + (y0 + y) * IMG_W + x0;
        *(float4*)dst       = make_float4(o8[0], o8[1], o8[2], o8[3]);
        *(float4*)(dst + 4) = make_float4(o8[4], o8[5], o8[6], o8[7]);
    }
}

// =====================================================================
// Kernel 2b: out[b,o,p] = sum_c W_out[o,c] * g[b,c,p]
// gsT rows (1024B) chunk-swizzled: g loads conflict-free.
// =====================================================================
__global__ void __launch_bounds__(256, 2) k_proj_out(const float* __restrict__ W_out,
                                                     float* __restrict__ out) {
    __shared__ float gsT[32 * 256];     // [kk][px swizzled] 32768 B
    __shared__ float Wo2[32 * 128];     // [kk][64 o dup]    16384 B

    const int t  = threadIdx.x;
    const int b  = blockIdx.z;
    const int p0 = blockIdx.x * 256;

    const int tx = t & 31;              // px group
    const int ty = t >> 5;              // o group 0..7
    const int pb = tx * 8;
    const int ob = ty * 8;
    const int q0 = swz8(2 * tx) * 4;
    const int q1 = swz8(2 * tx + 1) * 4;

    unsigned long long acc[8][4];
#pragma unroll
    for (int i = 0; i < 8; i++)
#pragma unroll
        for (int j = 0; j < 4; j++) acc[i][j] = 0ull;

    const float* gb = g_g + ((size_t)b * HID) * HW;

#pragma unroll 1
    for (int ph = 0; ph < 4; ph++) {
        const int c0 = ph * 32;
        // stage g tile: 32 ch x 64 chunks = 2048, 8/thread (swizzled dst)
#pragma unroll
        for (int i = 0; i < 8; i++) {
            int idx = t + i * 256;
            int kk = idx >> 6, ch = idx & 63;
            cp16(&gsT[(kk * 64 + swz8(ch)) * 4],
                 gb + (size_t)(c0 + kk) * HW + p0 + ch * 4, 16);
        }
        cp_commit();
        // stage duplicated weights: 32 kk x 64 o
#pragma unroll
        for (int i = 0; i < 8; i++) {
            int idx = t + i * 256;
            int kk = idx >> 6, o = idx & 63;
            float w = W_out[o * HID + c0 + kk];
            *(float2*)&Wo2[kk * 128 + o * 2] = make_float2(w, w);
        }
        cp_wait<0>();
        __syncthreads();

#pragma unroll 8
        for (int kk = 0; kk < 32; kk++) {
            const ulonglong2* Wr = (const ulonglong2*)&Wo2[kk * 128 + ob * 2];
            ulonglong2 w01 = Wr[0], w23 = Wr[1], w45 = Wr[2], w67 = Wr[3];
            ulonglong2 gA = *(const ulonglong2*)&gsT[kk * 256 + q0];
            ulonglong2 gB = *(const ulonglong2*)&gsT[kk * 256 + q1];

            acc[0][0] = fma2(w01.x, gA.x, acc[0][0]);
            acc[0][1] = fma2(w01.x, gA.y, acc[0][1]);
            acc[0][2] = fma2(w01.x, gB.x, acc[0][2]);
            acc[0][3] = fma2(w01.x, gB.y, acc[0][3]);
            acc[1][0] = fma2(w01.y, gA.x, acc[1][0]);
            acc[1][1] = fma2(w01.y, gA.y, acc[1][1]);
            acc[1][2] = fma2(w01.y, gB.x, acc[1][2]);
            acc[1][3] = fma2(w01.y, gB.y, acc[1][3]);
            acc[2][0] = fma2(w23.x, gA.x, acc[2][0]);
            acc[2][1] = fma2(w23.x, gA.y, acc[2][1]);
            acc[2][2] = fma2(w23.x, gB.x, acc[2][2]);
            acc[2][3] = fma2(w23.x, gB.y, acc[2][3]);
            acc[3][0] = fma2(w23.y, gA.x, acc[3][0]);
            acc[3][1] = fma2(w23.y, gA.y, acc[3][1]);
            acc[3][2] = fma2(w23.y, gB.x, acc[3][2]);
            acc[3][3] = fma2(w23.y, gB.y, acc[3][3]);
            acc[4][0] = fma2(w45.x, gA.x, acc[4][0]);
            acc[4][1] = fma2(w45.x, gA.y, acc[4][1]);
            acc[4][2] = fma2(w45.x, gB.x, acc[4][2]);
            acc[4][3] = fma2(w45.x, gB.y, acc[4][3]);
            acc[5][0] = fma2(w45.y, gA.x, acc[5][0]);
            acc[5][1] = fma2(w45.y, gA.y, acc[5][1]);
            acc[5][2] = fma2(w45.y, gB.x, acc[5][2]);
            acc[5][3] = fma2(w45.y, gB.y, acc[5][3]);
            acc[6][0] = fma2(w67.x, gA.x, acc[6][0]);
            acc[6][1] = fma2(w67.x, gA.y, acc[6][1]);
            acc[6][2] = fma2(w67.x, gB.x, acc[6][2]);
            acc[6][3] = fma2(w67.x, gB.y, acc[6][3]);
            acc[7][0] = fma2(w67.y, gA.x, acc[7][0]);
            acc[7][1] = fma2(w67.y, gA.y, acc[7][1]);
            acc[7][2] = fma2(w67.y, gB.x, acc[7][2]);
            acc[7][3] = fma2(w67.y, gB.y, acc[7][3]);
        }
        if (ph < 3) __syncthreads();
    }

    // Epilogue: 8 o-rows x 8 px
#pragma unroll
    for (int oi = 0; oi < 8; oi++) {
        float* dst = out + ((size_t)b * DIM + (ob + oi)) * HW + p0 + pb;
        ulonglong2 v0, v1;
        v0.x = acc[oi][0]; v0.y = acc[oi][1];
        v1.x = acc[oi][2]; v1.y = acc[oi][3];
        ((ulonglong2*)dst)[0] = v0;
        ((ulonglong2*)dst)[1] = v1;
    }
}

// =====================================================================
// Launch (graph-capturable, no allocs)
// Inputs: x, gen_kernel, W_in, dw_kernel, lambda_dw, W_out
// =====================================================================
extern "C" void kernel_launch(void* const* d_in, const int* in_sizes, int n_in,
                              void* d_out, int out_size) {
    const float* x     = (const float*)d_in[0];
    const float* genk  = (const float*)d_in[1];
    const float* W_in  = (const float*)d_in[2];
    const float* dwk   = (const float*)d_in[3];
    const float* lam   = (const float*)d_in[4];
    const float* W_out = (const float*)d_in[5];
    float* out = (float*)d_out;

    dim3 g1(HW / 128, HID / 64, BATCH);     // (128, 2, 8)
    k_proj_in<<<g1, 256>>>(x, W_in);

    dim3 g2(HID, IMG_H / 32, BATCH);        // (128, 4, 8)
    k_conv_gelu<<<g2, 256>>>(genk, dwk, lam);

    dim3 g3(HW / 256, 1, BATCH);            // (64, 1, 8)
    k_proj_out<<<g3, 256>>>(W_out, out);
}

// round 11
// speedup vs baseline: 2.5738x; 1.0423x over previous
#include <cuda_runtime.h>
#include <math.h>

// Problem constants
#define BATCH 8
#define DIM   64
#define HID   128
#define C2    256      // 2*HID
#define IMG_H 128
#define IMG_W 128
#define HW    16384    // 128*128

// Scratch u, INTERLEAVED: g_u2[b][cp][px] holds pair (u[cp], u[cp+128]),
// cp in 0..127.  (B, 128, HW, 2) fp32 = 128 MiB device global (no alloc).
__device__ float g_u2[(size_t)BATCH * HID * HW * 2];
// Scratch g = gelu(x1)*x2, planar (B, HID, HW) fp32 = 64 MiB.
__device__ float g_g[(size_t)BATCH * HID * HW];

// ---------------- packed f32x2 helpers (sm_103a FFMA2) ----------------
__device__ __forceinline__ unsigned long long pk2(float v) {
    unsigned long long r;
    asm("mov.b64 %0, {%1, %1};" : "=l"(r) : "f"(v));
    return r;
}
__device__ __forceinline__ unsigned long long fma2(unsigned long long a,
                                                   unsigned long long b,
                                                   unsigned long long c) {
    unsigned long long d;
    asm("fma.rn.f32x2 %0, %1, %2, %3;" : "=l"(d) : "l"(a), "l"(b), "l"(c));
    return d;
}
__device__ __forceinline__ void upk(unsigned long long v, float& lo, float& hi) {
    asm("mov.b64 {%0, %1}, %2;" : "=f"(lo), "=f"(hi) : "l"(v));
}

// ---------------- cp.async helpers ----------------
__device__ __forceinline__ void cp16(void* smem_dst, const void* gmem_src, int src_sz) {
    unsigned int s = (unsigned int)__cvta_generic_to_shared(smem_dst);
    asm volatile("cp.async.ca.shared.global [%0], [%1], 16, %2;\n"
                 :: "r"(s), "l"(gmem_src), "r"(src_sz));
}
__device__ __forceinline__ void cp_commit() {
    asm volatile("cp.async.commit_group;\n");
}
template <int N>
__device__ __forceinline__ void cp_wait() {
    asm volatile("cp.async.wait_group %0;\n" :: "n"(N));
}

// 16B-chunk XOR swizzles (conflict-free stride-32B/64B access)
__device__ __forceinline__ int swz4(int c) { return c ^ ((c >> 3) & 3); }  // 512B row
__device__ __forceinline__ int swz8(int c) { return c ^ ((c >> 3) & 7); }  // 1024B+ row

// =====================================================================
// Kernel 1: u[b,o,p] = sum_k W_in[o,k] * x[b,k,p], stored interleaved.
// FULL-K prefetch: all 64 k staged once (xs 32KB + dup weights 64KB,
// 96KB dynamic smem), then 64 k-iterations with NO mid-kernel barrier.
// =====================================================================
__global__ void __launch_bounds__(256, 2) k_proj_in(const float* __restrict__ x,
                                                    const float* __restrict__ W_in) {
    extern __shared__ float smem1[];
    float* xs  = smem1;            // [64][128 swizzled]   32768 B
    float* Ws2 = smem1 + 8192;     // [64][128 float2 dup] 65536 B

    const int t   = threadIdx.x;
    const int b   = blockIdx.z;
    const int cp0 = blockIdx.y * 64;
    const int p0  = blockIdx.x * 128;

    const int tx = t & 15;
    const int ty = t >> 4;
    const int pb = tx * 8;
    const int q0 = swz4(2 * tx) * 4;
    const int q1 = swz4(2 * tx + 1) * 4;

    // ---- prologue: LDG all weights first (latency overlaps cp.async) ----
    float4 wv[8];
#pragma unroll
    for (int i = 0; i < 8; i++) {
        int idx = t + i * 256;            // 0..2047
        int j   = idx & 127;              // channel slot
        int kq  = idx >> 7;               // 0..15 (4 k each)
        int ch  = cp0 + j + ((j < 64) ? 0 : 64);
        wv[i] = *(const float4*)&W_in[ch * 64 + kq * 4];
    }
    // stage all x: 64 ch x 32 chunks = 2048 cp.asyncs, 8/thread
    const float* xg = x + ((size_t)b * DIM) * HW + p0;
#pragma unroll
    for (int i = 0; i < 8; i++) {
        int idx = t + i * 256;
        int kk  = idx >> 5;
        int c4  = idx & 31;
        cp16(&xs[(kk * 32 + swz4(c4)) * 4], xg + (size_t)kk * HW + c4 * 4, 16);
    }
    cp_commit();
    // STS duplicated weights
#pragma unroll
    for (int i = 0; i < 8; i++) {
        int idx = t + i * 256;
        int j   = idx & 127;
        int kq  = idx >> 7;
        float2* dst = (float2*)Ws2;
        dst[(kq * 4 + 0) * 128 + j] = make_float2(wv[i].x, wv[i].x);
        dst[(kq * 4 + 1) * 128 + j] = make_float2(wv[i].y, wv[i].y);
        dst[(kq * 4 + 2) * 128 + j] = make_float2(wv[i].z, wv[i].z);
        dst[(kq * 4 + 3) * 128 + j] = make_float2(wv[i].w, wv[i].w);
    }
    cp_wait<0>();
    __syncthreads();                      // the ONLY barrier in this kernel

    unsigned long long aa[4][4], ab[4][4];
#pragma unroll
    for (int i = 0; i < 4; i++)
#pragma unroll
        for (int j = 0; j < 4; j++) { aa[i][j] = 0ull; ab[i][j] = 0ull; }

#pragma unroll 8
    for (int kk = 0; kk < 64; kk++) {
        const float* Wr = Ws2 + kk * 256;
        ulonglong2 wa01 = *(const ulonglong2*)(Wr + 8 * ty);
        ulonglong2 wa23 = *(const ulonglong2*)(Wr + 8 * ty + 4);
        ulonglong2 wb01 = *(const ulonglong2*)(Wr + 128 + 8 * ty);
        ulonglong2 wb23 = *(const ulonglong2*)(Wr + 128 + 8 * ty + 4);
        ulonglong2 xv0  = *(const ulonglong2*)(xs + kk * 128 + q0);
        ulonglong2 xv1  = *(const ulonglong2*)(xs + kk * 128 + q1);

        aa[0][0] = fma2(wa01.x, xv0.x, aa[0][0]);
        aa[0][1] = fma2(wa01.x, xv0.y, aa[0][1]);
        aa[0][2] = fma2(wa01.x, xv1.x, aa[0][2]);
        aa[0][3] = fma2(wa01.x, xv1.y, aa[0][3]);
        aa[1][0] = fma2(wa01.y, xv0.x, aa[1][0]);
        aa[1][1] = fma2(wa01.y, xv0.y, aa[1][1]);
        aa[1][2] = fma2(wa01.y, xv1.x, aa[1][2]);
        aa[1][3] = fma2(wa01.y, xv1.y, aa[1][3]);
        aa[2][0] = fma2(wa23.x, xv0.x, aa[2][0]);
        aa[2][1] = fma2(wa23.x, xv0.y, aa[2][1]);
        aa[2][2] = fma2(wa23.x, xv1.x, aa[2][2]);
        aa[2][3] = fma2(wa23.x, xv1.y, aa[2][3]);
        aa[3][0] = fma2(wa23.y, xv0.x, aa[3][0]);
        aa[3][1] = fma2(wa23.y, xv0.y, aa[3][1]);
        aa[3][2] = fma2(wa23.y, xv1.x, aa[3][2]);
        aa[3][3] = fma2(wa23.y, xv1.y, aa[3][3]);

        ab[0][0] = fma2(wb01.x, xv0.x, ab[0][0]);
        ab[0][1] = fma2(wb01.x, xv0.y, ab[0][1]);
        ab[0][2] = fma2(wb01.x, xv1.x, ab[0][2]);
        ab[0][3] = fma2(wb01.x, xv1.y, ab[0][3]);
        ab[1][0] = fma2(wb01.y, xv0.x, ab[1][0]);
        ab[1][1] = fma2(wb01.y, xv0.y, ab[1][1]);
        ab[1][2] = fma2(wb01.y, xv1.x, ab[1][2]);
        ab[1][3] = fma2(wb01.y, xv1.y, ab[1][3]);
        ab[2][0] = fma2(wb23.x, xv0.x, ab[2][0]);
        ab[2][1] = fma2(wb23.x, xv0.y, ab[2][1]);
        ab[2][2] = fma2(wb23.x, xv1.x, ab[2][2]);
        ab[2][3] = fma2(wb23.x, xv1.y, ab[2][3]);
        ab[3][0] = fma2(wb23.y, xv0.x, ab[3][0]);
        ab[3][1] = fma2(wb23.y, xv0.y, ab[3][1]);
        ab[3][2] = fma2(wb23.y, xv1.x, ab[3][2]);
        ab[3][3] = fma2(wb23.y, xv1.y, ab[3][3]);
    }

#pragma unroll
    for (int ci = 0; ci < 4; ci++) {
        int cp = cp0 + 4 * ty + ci;
        float* base = g_u2 + (((size_t)b * HID + cp) * HW + p0 + pb) * 2;
#pragma unroll
        for (int j = 0; j < 4; j++) {
            float alo, ahi, blo, bhi;
            upk(aa[ci][j], alo, ahi);
            upk(ab[ci][j], blo, bhi);
            *(float4*)(base + 4 * j) = make_float4(alo, blo, ahi, bhi);
        }
    }
}

// =====================================================================
// Kernel 2a: dynamic depthwise 3x3 + exact GELU gate -> g (planar).
// (unchanged from round 10 — passing, swizzled, conflict-free)
// =====================================================================
#define AROW 264
__global__ void __launch_bounds__(256) k_conv_gelu(const float* __restrict__ genk,
                                                   const float* __restrict__ dwkg,
                                                   const float* __restrict__ lam) {
    __shared__ float halo[34 * AROW];     // 35904 B
    __shared__ float kc2s[18];

    const int t  = threadIdx.x;
    const int cp = blockIdx.x;            // channel pair 0..127
    const int rb = blockIdx.y;            // row block 0..3
    const int b  = blockIdx.z;
    const int y0 = rb * 32;

    if (t < 18) {
        int tap = t >> 1, br = t & 1;
        int c = cp + br * HID;
        kc2s[tap * 2 + br] = dwkg[c * 9 + tap] + lam[c] * genk[b * (C2 * 9) + c * 9 + tap];
    }
    for (int i = t; i < 272; i += 256) {
        int rr = i >> 3, j = i & 7;
        halo[rr * AROW + ((j < 4) ? j : (256 + j))] = 0.0f;
    }
    {
        const float* src0 = g_u2 + ((size_t)b * HID + cp) * HW * 2;
#pragma unroll
        for (int i = 0; i < 9; i++) {
            int idx = t + i * 256;
            if (idx < 2176) {
                int rr = idx >> 6, ch = idx & 63;
                int gy = y0 - 1 + rr;
                bool ok = (unsigned)gy < 128u;
                cp16(&halo[rr * AROW + swz8(1 + ch) * 4],
                     src0 + (size_t)(ok ? gy : 0) * 256 + ch * 4, ok ? 16 : 0);
            }
        }
        cp_commit();
    }
    cp_wait<0>();
    __syncthreads();

    unsigned long long tap[9];
#pragma unroll
    for (int i = 0; i < 9; i++) tap[i] = *(const unsigned long long*)&kc2s[2 * i];

    const int s  = t & 15;
    const int x0 = s * 8;
    const int yb = t >> 4;
    int qof[6];
#pragma unroll
    for (int j = 0; j < 6; j++) qof[j] = swz8(4 * s + j) * 4;

    float* gbase = g_g + ((size_t)b * HID + cp) * HW;

#pragma unroll
    for (int half = 0; half < 2; half++) {
        int y = yb + half * 16;
        unsigned long long v[8];
#pragma unroll
        for (int j = 0; j < 8; j++) v[j] = 0ull;

#pragma unroll
        for (int r = 0; r < 3; r++) {
            const float* Hrow = &halo[(y + r) * AROW];
            unsigned long long p[12];
#pragma unroll
            for (int j = 0; j < 6; j++) {
                ulonglong2 qq = *(const ulonglong2*)&Hrow[qof[j]];
                p[2 * j]     = qq.x;
                p[2 * j + 1] = qq.y;
            }
#pragma unroll
            for (int dx = 0; dx < 3; dx++) {
                unsigned long long tp_ = tap[r * 3 + dx];
#pragma unroll
                for (int j = 0; j < 8; j++)
                    v[j] = fma2(tp_, p[j + dx + 1], v[j]);
            }
        }
        float o8[8];
#pragma unroll
        for (int j = 0; j < 8; j++) {
            float va, vb;
            upk(v[j], va, vb);
            o8[j] = 0.5f * va * (1.0f + erff(va * 0.7071067811865476f)) * vb;
        }
        float* dst = gbase + (y0 + y) * IMG_W + x0;
        *(float4*)dst       = make_float4(o8[0], o8[1], o8[2], o8[3]);
        *(float4*)(dst + 4) = make_float4(o8[4], o8[5], o8[6], o8[7]);
    }
}

// =====================================================================
// Kernel 2b: out[b,o,p] = sum_c W_out[o,c] * g[b,c,p]
// Double-buffered pipeline (96KB dynamic smem): phase p+1 staged
// (cp.async + weight LDG) BEFORE computing phase p — no exposed latency.
// =====================================================================
__global__ void __launch_bounds__(256, 2) k_proj_out(const float* __restrict__ W_out,
                                                     float* __restrict__ out) {
    extern __shared__ float smem2[];
    float* gsT = smem2;            // [2][32*256 swizzled]  65536 B
    float* Wo2 = smem2 + 16384;    // [2][32*128 dup]       32768 B

    const int t  = threadIdx.x;
    const int b  = blockIdx.z;
    const int p0 = blockIdx.x * 256;

    const int tx = t & 31;
    const int ty = t >> 5;
    const int pb = tx * 8;
    const int ob = ty * 8;
    const int q0 = swz8(2 * tx) * 4;
    const int q1 = swz8(2 * tx + 1) * 4;

    const float* gb = g_g + ((size_t)b * HID) * HW;

    // staging helpers
    auto stage_g = [&](int ph, int buf) {
        float* dstb = gsT + buf * 8192;
#pragma unroll
        for (int i = 0; i < 8; i++) {
            int idx = t + i * 256;
            int kk = idx >> 6, ch = idx & 63;
            cp16(&dstb[(kk * 64 + swz8(ch)) * 4],
                 gb + (size_t)(ph * 32 + kk) * HW + p0 + ch * 4, 16);
        }
        cp_commit();
    };
    auto w_ldg = [&](int ph, float* w8) {
#pragma unroll
        for (int i = 0; i < 8; i++) {
            int idx = t + i * 256;
            int kk = idx >> 6, o = idx & 63;
            w8[i] = W_out[o * HID + ph * 32 + kk];
        }
    };
    auto w_sts = [&](int buf, const float* w8) {
        float* dstb = Wo2 + buf * 4096;
#pragma unroll
        for (int i = 0; i < 8; i++) {
            int idx = t + i * 256;
            int kk = idx >> 6, o = idx & 63;
            *(float2*)&dstb[kk * 128 + o * 2] = make_float2(w8[i], w8[i]);
        }
    };

    unsigned long long acc[8][4];
#pragma unroll
    for (int i = 0; i < 8; i++)
#pragma unroll
        for (int j = 0; j < 4; j++) acc[i][j] = 0ull;

    // prologue: phase 0 into buf 0
    float wreg[8];
    stage_g(0, 0);
    w_ldg(0, wreg);
    w_sts(0, wreg);
    cp_wait<0>();
    __syncthreads();

#pragma unroll 1
    for (int ph = 0; ph < 4; ph++) {
        const int buf = ph & 1;
        if (ph < 3) {                       // prefetch next phase
            stage_g(ph + 1, buf ^ 1);
            w_ldg(ph + 1, wreg);
        }

        const float* gB = gsT + buf * 8192;
        const float* wB = Wo2 + buf * 4096;
#pragma unroll 8
        for (int kk = 0; kk < 32; kk++) {
            const ulonglong2* Wr = (const ulonglong2*)&wB[kk * 128 + ob * 2];
            ulonglong2 w01 = Wr[0], w23 = Wr[1], w45 = Wr[2], w67 = Wr[3];
            ulonglong2 gA = *(const ulonglong2*)&gB[kk * 256 + q0];
            ulonglong2 gBv = *(const ulonglong2*)&gB[kk * 256 + q1];

            acc[0][0] = fma2(w01.x, gA.x, acc[0][0]);
            acc[0][1] = fma2(w01.x, gA.y, acc[0][1]);
            acc[0][2] = fma2(w01.x, gBv.x, acc[0][2]);
            acc[0][3] = fma2(w01.x, gBv.y, acc[0][3]);
            acc[1][0] = fma2(w01.y, gA.x, acc[1][0]);
            acc[1][1] = fma2(w01.y, gA.y, acc[1][1]);
            acc[1][2] = fma2(w01.y, gBv.x, acc[1][2]);
            acc[1][3] = fma2(w01.y, gBv.y, acc[1][3]);
            acc[2][0] = fma2(w23.x, gA.x, acc[2][0]);
            acc[2][1] = fma2(w23.x, gA.y, acc[2][1]);
            acc[2][2] = fma2(w23.x, gBv.x, acc[2][2]);
            acc[2][3] = fma2(w23.x, gBv.y, acc[2][3]);
            acc[3][0] = fma2(w23.y, gA.x, acc[3][0]);
            acc[3][1] = fma2(w23.y, gA.y, acc[3][1]);
            acc[3][2] = fma2(w23.y, gBv.x, acc[3][2]);
            acc[3][3] = fma2(w23.y, gBv.y, acc[3][3]);
            acc[4][0] = fma2(w45.x, gA.x, acc[4][0]);
            acc[4][1] = fma2(w45.x, gA.y, acc[4][1]);
            acc[4][2] = fma2(w45.x, gBv.x, acc[4][2]);
            acc[4][3] = fma2(w45.x, gBv.y, acc[4][3]);
            acc[5][0] = fma2(w45.y, gA.x, acc[5][0]);
            acc[5][1] = fma2(w45.y, gA.y, acc[5][1]);
            acc[5][2] = fma2(w45.y, gBv.x, acc[5][2]);
            acc[5][3] = fma2(w45.y, gBv.y, acc[5][3]);
            acc[6][0] = fma2(w67.x, gA.x, acc[6][0]);
            acc[6][1] = fma2(w67.x, gA.y, acc[6][1]);
            acc[6][2] = fma2(w67.x, gBv.x, acc[6][2]);
            acc[6][3] = fma2(w67.x, gBv.y, acc[6][3]);
            acc[7][0] = fma2(w67.y, gA.x, acc[7][0]);
            acc[7][1] = fma2(w67.y, gA.y, acc[7][1]);
            acc[7][2] = fma2(w67.y, gBv.x, acc[7][2]);
            acc[7][3] = fma2(w67.y, gBv.y, acc[7][3]);
        }

        if (ph < 3) {
            w_sts(buf ^ 1, wreg);           // other buffer: no race with compute
            cp_wait<0>();
            __syncthreads();
        }
    }

    // Epilogue: 8 o-rows x 8 px
#pragma unroll
    for (int oi = 0; oi < 8; oi++) {
        float* dst = out + ((size_t)b * DIM + (ob + oi)) * HW + p0 + pb;
        ulonglong2 v0, v1;
        v0.x = acc[oi][0]; v0.y = acc[oi][1];
        v1.x = acc[oi][2]; v1.y = acc[oi][3];
        ((ulonglong2*)dst)[0] = v0;
        ((ulonglong2*)dst)[1] = v1;
    }
}

// =====================================================================
// Launch (graph-capturable, no allocs)
// Inputs: x, gen_kernel, W_in, dw_kernel, lambda_dw, W_out
// =====================================================================
extern "C" void kernel_launch(void* const* d_in, const int* in_sizes, int n_in,
                              void* d_out, int out_size) {
    const float* x     = (const float*)d_in[0];
    const float* genk  = (const float*)d_in[1];
    const float* W_in  = (const float*)d_in[2];
    const float* dwk   = (const float*)d_in[3];
    const float* lam   = (const float*)d_in[4];
    const float* W_out = (const float*)d_in[5];
    float* out = (float*)d_out;

    static int attr_done = 0;
    if (!attr_done) {
        cudaFuncSetAttribute(k_proj_in,  cudaFuncAttributeMaxDynamicSharedMemorySize, 98304);
        cudaFuncSetAttribute(k_proj_out, cudaFuncAttributeMaxDynamicSharedMemorySize, 98304);
        attr_done = 1;
    }

    dim3 g1(HW / 128, HID / 64, BATCH);     // (128, 2, 8)
    k_proj_in<<<g1, 256, 98304>>>(x, W_in);

    dim3 g2(HID, IMG_H / 32, BATCH);        // (128, 4, 8)
    k_conv_gelu<<<g2, 256>>>(genk, dwk, lam);

    dim3 g3(HW / 256, 1, BATCH);            // (64, 1, 8)
    k_proj_out<<<g3, 256, 98304>>>(W_out, out);
}

// round 12
// speedup vs baseline: 2.9451x; 1.1442x over previous
#include <cuda_runtime.h>
#include <math.h>

// Problem constants
#define BATCH 8
#define DIM   64
#define HID   128
#define C2    256      // 2*HID
#define IMG_H 128
#define IMG_W 128
#define HW    16384    // 128*128

// Scratch u, INTERLEAVED: g_u2[b][cp][px] holds pair (u[cp], u[cp+128]),
// cp in 0..127.  (B, 128, HW, 2) fp32 = 128 MiB device global (no alloc).
__device__ float g_u2[(size_t)BATCH * HID * HW * 2];
// Scratch g = gelu(x1)*x2, planar (B, HID, HW) fp32 = 64 MiB.
__device__ float g_g[(size_t)BATCH * HID * HW];

// ---------------- packed f32x2 helpers (sm_103a FFMA2) ----------------
__device__ __forceinline__ unsigned long long pk2(float v) {
    unsigned long long r;
    asm("mov.b64 %0, {%1, %1};" : "=l"(r) : "f"(v));
    return r;
}
__device__ __forceinline__ unsigned long long fma2(unsigned long long a,
                                                   unsigned long long b,
                                                   unsigned long long c) {
    unsigned long long d;
    asm("fma.rn.f32x2 %0, %1, %2, %3;" : "=l"(d) : "l"(a), "l"(b), "l"(c));
    return d;
}
__device__ __forceinline__ void upk(unsigned long long v, float& lo, float& hi) {
    asm("mov.b64 {%0, %1}, %2;" : "=f"(lo), "=f"(hi) : "l"(v));
}

// ---------------- cp.async helpers ----------------
__device__ __forceinline__ void cp16(void* smem_dst, const void* gmem_src, int src_sz) {
    unsigned int s = (unsigned int)__cvta_generic_to_shared(smem_dst);
    asm volatile("cp.async.ca.shared.global [%0], [%1], 16, %2;\n"
                 :: "r"(s), "l"(gmem_src), "r"(src_sz));
}
__device__ __forceinline__ void cp_commit() {
    asm volatile("cp.async.commit_group;\n");
}
template <int N>
__device__ __forceinline__ void cp_wait() {
    asm volatile("cp.async.wait_group %0;\n" :: "n"(N));
}

// 16B-chunk XOR swizzles (conflict-free stride-32B/64B access)
__device__ __forceinline__ int swz4(int c) { return c ^ ((c >> 3) & 3); }  // 512B row
__device__ __forceinline__ int swz8(int c) { return c ^ ((c >> 3) & 7); }  // 1024B+ row

// =====================================================================
// Kernel 1: u[b,o,p] = sum_k W_in[o,k] * x[b,k,p], stored interleaved.
// FULL-K prefetch, UNDUPLICATED weights (scalar Wsa/Wsb, 32KB) packed
// with pk2 at use time: SMEM bytes per FFMA2 drop 3 -> 2.
// 64KB dynamic smem, single barrier, 64 k-iterations.
// =====================================================================
__global__ void __launch_bounds__(256, 2) k_proj_in(const float* __restrict__ x,
                                                    const float* __restrict__ W_in) {
    extern __shared__ float smem1[];
    float* xs  = smem1;            // [64][128 swizzled]  32768 B
    float* Wsa = smem1 + 8192;     // [64][64]            16384 B
    float* Wsb = smem1 + 12288;    // [64][64]            16384 B

    const int t   = threadIdx.x;
    const int b   = blockIdx.z;
    const int cp0 = blockIdx.y * 64;
    const int p0  = blockIdx.x * 128;

    const int tx = t & 15;
    const int ty = t >> 4;
    const int pb = tx * 8;
    const int q0 = swz4(2 * tx) * 4;
    const int q1 = swz4(2 * tx + 1) * 4;

    // ---- prologue: weight LDGs first (latency overlaps cp.async issue) ----
    float4 wva[4], wvb[4];
#pragma unroll
    for (int i = 0; i < 4; i++) {
        int idx = t + i * 256;            // 0..1023
        int j   = idx & 63;               // channel slot
        int kq  = idx >> 6;               // 0..15 (4 k each)
        wva[i] = *(const float4*)&W_in[(cp0 + j) * 64 + kq * 4];
        wvb[i] = *(const float4*)&W_in[(cp0 + 128 + j) * 64 + kq * 4];
    }
    // stage all x: 64 ch x 32 chunks = 2048 cp.asyncs, 8/thread
    const float* xg = x + ((size_t)b * DIM) * HW + p0;
#pragma unroll
    for (int i = 0; i < 8; i++) {
        int idx = t + i * 256;
        int kk  = idx >> 5;
        int c4  = idx & 31;
        cp16(&xs[(kk * 32 + swz4(c4)) * 4], xg + (size_t)kk * HW + c4 * 4, 16);
    }
    cp_commit();
    // STS scalar weights (transposed [k][ch])
#pragma unroll
    for (int i = 0; i < 4; i++) {
        int idx = t + i * 256;
        int j   = idx & 63;
        int kq  = idx >> 6;
        Wsa[(kq * 4 + 0) * 64 + j] = wva[i].x;
        Wsa[(kq * 4 + 1) * 64 + j] = wva[i].y;
        Wsa[(kq * 4 + 2) * 64 + j] = wva[i].z;
        Wsa[(kq * 4 + 3) * 64 + j] = wva[i].w;
        Wsb[(kq * 4 + 0) * 64 + j] = wvb[i].x;
        Wsb[(kq * 4 + 1) * 64 + j] = wvb[i].y;
        Wsb[(kq * 4 + 2) * 64 + j] = wvb[i].z;
        Wsb[(kq * 4 + 3) * 64 + j] = wvb[i].w;
    }
    cp_wait<0>();
    __syncthreads();                      // the ONLY barrier in this kernel

    unsigned long long aa[4][4], ab[4][4];
#pragma unroll
    for (int i = 0; i < 4; i++)
#pragma unroll
        for (int j = 0; j < 4; j++) { aa[i][j] = 0ull; ab[i][j] = 0ull; }

#pragma unroll 8
    for (int kk = 0; kk < 64; kk++) {
        float4 wa = *(const float4*)&Wsa[kk * 64 + 4 * ty];
        float4 wb = *(const float4*)&Wsb[kk * 64 + 4 * ty];
        ulonglong2 xv0 = *(const ulonglong2*)(xs + kk * 128 + q0);
        ulonglong2 xv1 = *(const ulonglong2*)(xs + kk * 128 + q1);
        unsigned long long wa0 = pk2(wa.x), wa1 = pk2(wa.y),
                           wa2 = pk2(wa.z), wa3 = pk2(wa.w);
        unsigned long long wb0 = pk2(wb.x), wb1 = pk2(wb.y),
                           wb2 = pk2(wb.z), wb3 = pk2(wb.w);

        aa[0][0] = fma2(wa0, xv0.x, aa[0][0]);
        aa[0][1] = fma2(wa0, xv0.y, aa[0][1]);
        aa[0][2] = fma2(wa0, xv1.x, aa[0][2]);
        aa[0][3] = fma2(wa0, xv1.y, aa[0][3]);
        aa[1][0] = fma2(wa1, xv0.x, aa[1][0]);
        aa[1][1] = fma2(wa1, xv0.y, aa[1][1]);
        aa[1][2] = fma2(wa1, xv1.x, aa[1][2]);
        aa[1][3] = fma2(wa1, xv1.y, aa[1][3]);
        aa[2][0] = fma2(wa2, xv0.x, aa[2][0]);
        aa[2][1] = fma2(wa2, xv0.y, aa[2][1]);
        aa[2][2] = fma2(wa2, xv1.x, aa[2][2]);
        aa[2][3] = fma2(wa2, xv1.y, aa[2][3]);
        aa[3][0] = fma2(wa3, xv0.x, aa[3][0]);
        aa[3][1] = fma2(wa3, xv0.y, aa[3][1]);
        aa[3][2] = fma2(wa3, xv1.x, aa[3][2]);
        aa[3][3] = fma2(wa3, xv1.y, aa[3][3]);

        ab[0][0] = fma2(wb0, xv0.x, ab[0][0]);
        ab[0][1] = fma2(wb0, xv0.y, ab[0][1]);
        ab[0][2] = fma2(wb0, xv1.x, ab[0][2]);
        ab[0][3] = fma2(wb0, xv1.y, ab[0][3]);
        ab[1][0] = fma2(wb1, xv0.x, ab[1][0]);
        ab[1][1] = fma2(wb1, xv0.y, ab[1][1]);
        ab[1][2] = fma2(wb1, xv1.x, ab[1][2]);
        ab[1][3] = fma2(wb1, xv1.y, ab[1][3]);
        ab[2][0] = fma2(wb2, xv0.x, ab[2][0]);
        ab[2][1] = fma2(wb2, xv0.y, ab[2][1]);
        ab[2][2] = fma2(wb2, xv1.x, ab[2][2]);
        ab[2][3] = fma2(wb2, xv1.y, ab[2][3]);
        ab[3][0] = fma2(wb3, xv0.x, ab[3][0]);
        ab[3][1] = fma2(wb3, xv0.y, ab[3][1]);
        ab[3][2] = fma2(wb3, xv1.x, ab[3][2]);
        ab[3][3] = fma2(wb3, xv1.y, ab[3][3]);
    }

#pragma unroll
    for (int ci = 0; ci < 4; ci++) {
        int cp = cp0 + 4 * ty + ci;
        float* base = g_u2 + (((size_t)b * HID + cp) * HW + p0 + pb) * 2;
#pragma unroll
        for (int j = 0; j < 4; j++) {
            float alo, ahi, blo, bhi;
            upk(aa[ci][j], alo, ahi);
            upk(ab[ci][j], blo, bhi);
            *(float4*)(base + 4 * j) = make_float4(alo, blo, ahi, bhi);
        }
    }
}

// =====================================================================
// Kernel 2a: dynamic depthwise 3x3 + exact GELU gate -> g (planar).
// (unchanged — passing, swizzled, conflict-free)
// =====================================================================
#define AROW 264
__global__ void __launch_bounds__(256) k_conv_gelu(const float* __restrict__ genk,
                                                   const float* __restrict__ dwkg,
                                                   const float* __restrict__ lam) {
    __shared__ float halo[34 * AROW];     // 35904 B
    __shared__ float kc2s[18];

    const int t  = threadIdx.x;
    const int cp = blockIdx.x;            // channel pair 0..127
    const int rb = blockIdx.y;            // row block 0..3
    const int b  = blockIdx.z;
    const int y0 = rb * 32;

    if (t < 18) {
        int tap = t >> 1, br = t & 1;
        int c = cp + br * HID;
        kc2s[tap * 2 + br] = dwkg[c * 9 + tap] + lam[c] * genk[b * (C2 * 9) + c * 9 + tap];
    }
    for (int i = t; i < 272; i += 256) {
        int rr = i >> 3, j = i & 7;
        halo[rr * AROW + ((j < 4) ? j : (256 + j))] = 0.0f;
    }
    {
        const float* src0 = g_u2 + ((size_t)b * HID + cp) * HW * 2;
#pragma unroll
        for (int i = 0; i < 9; i++) {
            int idx = t + i * 256;
            if (idx < 2176) {
                int rr = idx >> 6, ch = idx & 63;
                int gy = y0 - 1 + rr;
                bool ok = (unsigned)gy < 128u;
                cp16(&halo[rr * AROW + swz8(1 + ch) * 4],
                     src0 + (size_t)(ok ? gy : 0) * 256 + ch * 4, ok ? 16 : 0);
            }
        }
        cp_commit();
    }
    cp_wait<0>();
    __syncthreads();

    unsigned long long tap[9];
#pragma unroll
    for (int i = 0; i < 9; i++) tap[i] = *(const unsigned long long*)&kc2s[2 * i];

    const int s  = t & 15;
    const int x0 = s * 8;
    const int yb = t >> 4;
    int qof[6];
#pragma unroll
    for (int j = 0; j < 6; j++) qof[j] = swz8(4 * s + j) * 4;

    float* gbase = g_g + ((size_t)b * HID + cp) * HW;

#pragma unroll
    for (int half = 0; half < 2; half++) {
        int y = yb + half * 16;
        unsigned long long v[8];
#pragma unroll
        for (int j = 0; j < 8; j++) v[j] = 0ull;

#pragma unroll
        for (int r = 0; r < 3; r++) {
            const float* Hrow = &halo[(y + r) * AROW];
            unsigned long long p[12];
#pragma unroll
            for (int j = 0; j < 6; j++) {
                ulonglong2 qq = *(const ulonglong2*)&Hrow[qof[j]];
                p[2 * j]     = qq.x;
                p[2 * j + 1] = qq.y;
            }
#pragma unroll
            for (int dx = 0; dx < 3; dx++) {
                unsigned long long tp_ = tap[r * 3 + dx];
#pragma unroll
                for (int j = 0; j < 8; j++)
                    v[j] = fma2(tp_, p[j + dx + 1], v[j]);
            }
        }
        float o8[8];
#pragma unroll
        for (int j = 0; j < 8; j++) {
            float va, vb;
            upk(v[j], va, vb);
            o8[j] = 0.5f * va * (1.0f + erff(va * 0.7071067811865476f)) * vb;
        }
        float* dst = gbase + (y0 + y) * IMG_W + x0;
        *(float4*)dst       = make_float4(o8[0], o8[1], o8[2], o8[3]);
        *(float4*)(dst + 4) = make_float4(o8[4], o8[5], o8[6], o8[7]);
    }
}

// =====================================================================
// Kernel 2b: out[b,o,p] = sum_c W_out[o,c] * g[b,c,p]
// Double-buffered pipeline, UNDUPLICATED weights (warp-uniform loads)
// packed with pk2 at use time.  80KB dynamic smem.
// =====================================================================
__global__ void __launch_bounds__(256, 2) k_proj_out(const float* __restrict__ W_out,
                                                     float* __restrict__ out) {
    extern __shared__ float smem2[];
    float* gsT = smem2;            // [2][32*256 swizzled]  65536 B
    float* Wo  = smem2 + 16384;    // [2][32*64]            16384 B

    const int t  = threadIdx.x;
    const int b  = blockIdx.z;
    const int p0 = blockIdx.x * 256;

    const int tx = t & 31;
    const int ty = t >> 5;
    const int pb = tx * 8;
    const int ob = ty * 8;
    const int q0 = swz8(2 * tx) * 4;
    const int q1 = swz8(2 * tx + 1) * 4;

    const float* gb = g_g + ((size_t)b * HID) * HW;

    auto stage_g = [&](int ph, int buf) {
        float* dstb = gsT + buf * 8192;
#pragma unroll
        for (int i = 0; i < 8; i++) {
            int idx = t + i * 256;
            int kk = idx >> 6, ch = idx & 63;
            cp16(&dstb[(kk * 64 + swz8(ch)) * 4],
                 gb + (size_t)(ph * 32 + kk) * HW + p0 + ch * 4, 16);
        }
        cp_commit();
    };
    auto w_ldg = [&](int ph, float* w8) {
#pragma unroll
        for (int i = 0; i < 8; i++) {
            int idx = t + i * 256;
            int kk = idx >> 6, o = idx & 63;
            w8[i] = W_out[o * HID + ph * 32 + kk];
        }
    };
    auto w_sts = [&](int buf, const float* w8) {
        float* dstb = Wo + buf * 2048;
#pragma unroll
        for (int i = 0; i < 8; i++) {
            int idx = t + i * 256;
            int kk = idx >> 6, o = idx & 63;
            dstb[kk * 64 + o] = w8[i];
        }
    };

    unsigned long long acc[8][4];
#pragma unroll
    for (int i = 0; i < 8; i++)
#pragma unroll
        for (int j = 0; j < 4; j++) acc[i][j] = 0ull;

    float wreg[8];
    stage_g(0, 0);
    w_ldg(0, wreg);
    w_sts(0, wreg);
    cp_wait<0>();
    __syncthreads();

#pragma unroll 1
    for (int ph = 0; ph < 4; ph++) {
        const int buf = ph & 1;
        if (ph < 3) {
            stage_g(ph + 1, buf ^ 1);
            w_ldg(ph + 1, wreg);
        }

        const float* gB = gsT + buf * 8192;
        const float* wB = Wo + buf * 2048;
#pragma unroll 8
        for (int kk = 0; kk < 32; kk++) {
            float4 w0 = *(const float4*)&wB[kk * 64 + ob];       // warp-uniform
            float4 w1 = *(const float4*)&wB[kk * 64 + ob + 4];   // warp-uniform
            ulonglong2 gA  = *(const ulonglong2*)&gB[kk * 256 + q0];
            ulonglong2 gBv = *(const ulonglong2*)&gB[kk * 256 + q1];
            unsigned long long wp0 = pk2(w0.x), wp1 = pk2(w0.y),
                               wp2 = pk2(w0.z), wp3 = pk2(w0.w),
                               wp4 = pk2(w1.x), wp5 = pk2(w1.y),
                               wp6 = pk2(w1.z), wp7 = pk2(w1.w);

            acc[0][0] = fma2(wp0, gA.x, acc[0][0]);
            acc[0][1] = fma2(wp0, gA.y, acc[0][1]);
            acc[0][2] = fma2(wp0, gBv.x, acc[0][2]);
            acc[0][3] = fma2(wp0, gBv.y, acc[0][3]);
            acc[1][0] = fma2(wp1, gA.x, acc[1][0]);
            acc[1][1] = fma2(wp1, gA.y, acc[1][1]);
            acc[1][2] = fma2(wp1, gBv.x, acc[1][2]);
            acc[1][3] = fma2(wp1, gBv.y, acc[1][3]);
            acc[2][0] = fma2(wp2, gA.x, acc[2][0]);
            acc[2][1] = fma2(wp2, gA.y, acc[2][1]);
            acc[2][2] = fma2(wp2, gBv.x, acc[2][2]);
            acc[2][3] = fma2(wp2, gBv.y, acc[2][3]);
            acc[3][0] = fma2(wp3, gA.x, acc[3][0]);
            acc[3][1] = fma2(wp3, gA.y, acc[3][1]);
            acc[3][2] = fma2(wp3, gBv.x, acc[3][2]);
            acc[3][3] = fma2(wp3, gBv.y, acc[3][3]);
            acc[4][0] = fma2(wp4, gA.x, acc[4][0]);
            acc[4][1] = fma2(wp4, gA.y, acc[4][1]);
            acc[4][2] = fma2(wp4, gBv.x, acc[4][2]);
            acc[4][3] = fma2(wp4, gBv.y, acc[4][3]);
            acc[5][0] = fma2(wp5, gA.x, acc[5][0]);
            acc[5][1] = fma2(wp5, gA.y, acc[5][1]);
            acc[5][2] = fma2(wp5, gBv.x, acc[5][2]);
            acc[5][3] = fma2(wp5, gBv.y, acc[5][3]);
            acc[6][0] = fma2(wp6, gA.x, acc[6][0]);
            acc[6][1] = fma2(wp6, gA.y, acc[6][1]);
            acc[6][2] = fma2(wp6, gBv.x, acc[6][2]);
            acc[6][3] = fma2(wp6, gBv.y, acc[6][3]);
            acc[7][0] = fma2(wp7, gA.x, acc[7][0]);
            acc[7][1] = fma2(wp7, gA.y, acc[7][1]);
            acc[7][2] = fma2(wp7, gBv.x, acc[7][2]);
            acc[7][3] = fma2(wp7, gBv.y, acc[7][3]);
        }

        if (ph < 3) {
            w_sts(buf ^ 1, wreg);
            cp_wait<0>();
            __syncthreads();
        }
    }

#pragma unroll
    for (int oi = 0; oi < 8; oi++) {
        float* dst = out + ((size_t)b * DIM + (ob + oi)) * HW + p0 + pb;
        ulonglong2 v0, v1;
        v0.x = acc[oi][0]; v0.y = acc[oi][1];
        v1.x = acc[oi][2]; v1.y = acc[oi][3];
        ((ulonglong2*)dst)[0] = v0;
        ((ulonglong2*)dst)[1] = v1;
    }
}

// =====================================================================
// Launch (graph-capturable, no allocs)
// Inputs: x, gen_kernel, W_in, dw_kernel, lambda_dw, W_out
// =====================================================================
extern "C" void kernel_launch(void* const* d_in, const int* in_sizes, int n_in,
                              void* d_out, int out_size) {
    const float* x     = (const float*)d_in[0];
    const float* genk  = (const float*)d_in[1];
    const float* W_in  = (const float*)d_in[2];
    const float* dwk   = (const float*)d_in[3];
    const float* lam   = (const float*)d_in[4];
    const float* W_out = (const float*)d_in[5];
    float* out = (float*)d_out;

    static int attr_done = 0;
    if (!attr_done) {
        cudaFuncSetAttribute(k_proj_in,  cudaFuncAttributeMaxDynamicSharedMemorySize, 65536);
        cudaFuncSetAttribute(k_proj_out, cudaFuncAttributeMaxDynamicSharedMemorySize, 81920);
        attr_done = 1;
    }

    dim3 g1(HW / 128, HID / 64, BATCH);     // (128, 2, 8)
    k_proj_in<<<g1, 256, 65536>>>(x, W_in);

    dim3 g2(HID, IMG_H / 32, BATCH);        // (128, 4, 8)
    k_conv_gelu<<<g2, 256>>>(genk, dwk, lam);

    dim3 g3(HW / 256, 1, BATCH);            // (64, 1, 8)
    k_proj_out<<<g3, 256, 81920>>>(W_out, out);
}